// round 1
// baseline (speedup 1.0000x reference)
#include <cuda_runtime.h>

#define EMB   1024
#define NH    16
#define HS    64
#define BATCH 4
#define SEQ   2048
#define MROWS (BATCH * SEQ)   // 8192

// Scratch (allocation-free rule: __device__ globals)
__device__ float g_q[BATCH * NH * SEQ * HS];     // [B][H][T][D]
__device__ float g_k[BATCH * NH * SEQ * HS];
__device__ float g_v[BATCH * NH * SEQ * HS];
__device__ float g_att[MROWS * EMB];             // [B][T][C] (head-concat layout)

// ---------------------------------------------------------------------------
// QKV GEMM: A[8192,1024] @ W[1024,3072] + bias, scatter into g_q/g_k/g_v
// 128x128 block tile, BK=8, 256 threads, 8x8 per-thread micro-tile
// ---------------------------------------------------------------------------
__global__ __launch_bounds__(256) void qkv_gemm_kernel(
    const float* __restrict__ A, const float* __restrict__ B,
    const float* __restrict__ bias)
{
    const int K = EMB, N = 3 * EMB;
    __shared__ float As[8][128];
    __shared__ float Bs[8][128];

    const int tid = threadIdx.x;
    const int tx = tid & 15, ty = tid >> 4;
    const int bm = blockIdx.y, bn = blockIdx.x;

    const int arow = tid >> 1, acol = (tid & 1) * 4;
    const int brow = tid >> 5, bcol = (tid & 31) * 4;
    const float* Aptr = A + (size_t)(bm * 128 + arow) * K + acol;
    const float* Bptr = B + (size_t)brow * N + bn * 128 + bcol;

    float acc[8][8];
#pragma unroll
    for (int i = 0; i < 8; i++)
#pragma unroll
        for (int j = 0; j < 8; j++) acc[i][j] = 0.f;

    for (int k0 = 0; k0 < K; k0 += 8) {
        float4 a4 = *(const float4*)(Aptr + k0);
        float4 b4 = *(const float4*)(Bptr + (size_t)k0 * N);
        As[acol + 0][arow] = a4.x;
        As[acol + 1][arow] = a4.y;
        As[acol + 2][arow] = a4.z;
        As[acol + 3][arow] = a4.w;
        *(float4*)&Bs[brow][bcol] = b4;
        __syncthreads();
#pragma unroll
        for (int kk = 0; kk < 8; kk++) {
            float a[8], b[8];
            *(float4*)(&a[0]) = *(const float4*)(&As[kk][ty * 4]);
            *(float4*)(&a[4]) = *(const float4*)(&As[kk][64 + ty * 4]);
            *(float4*)(&b[0]) = *(const float4*)(&Bs[kk][tx * 4]);
            *(float4*)(&b[4]) = *(const float4*)(&Bs[kk][64 + tx * 4]);
#pragma unroll
            for (int i = 0; i < 8; i++)
#pragma unroll
                for (int j = 0; j < 8; j++)
                    acc[i][j] = fmaf(a[i], b[j], acc[i][j]);
        }
        __syncthreads();
    }

#pragma unroll
    for (int i = 0; i < 8; i++) {
        int r  = (i < 4) ? ty * 4 + i : 64 + ty * 4 + (i - 4);
        int gm = bm * 128 + r;
        int bb = gm >> 11;              // / SEQ
        int t  = gm & (SEQ - 1);
#pragma unroll
        for (int j = 0; j < 8; j++) {
            int c  = (j < 4) ? tx * 4 + j : 64 + tx * 4 + (j - 4);
            int gn = bn * 128 + c;
            float val = acc[i][j] + bias[gn];
            int which = gn >> 10;       // 0=q 1=k 2=v
            int cc = gn & (EMB - 1);
            int h  = cc >> 6, d = cc & (HS - 1);
            float* dst = (which == 0) ? g_q : (which == 1 ? g_k : g_v);
            dst[(size_t)(((bb * NH + h) * SEQ) + t) * HS + d] = val;
        }
    }
}

// ---------------------------------------------------------------------------
// Out projection: g_att[8192,1024] @ W[1024,1024] + bias -> out
// ---------------------------------------------------------------------------
__global__ __launch_bounds__(256) void out_gemm_kernel(
    const float* __restrict__ B, const float* __restrict__ bias,
    float* __restrict__ out)
{
    const int K = EMB, N = EMB;
    __shared__ float As[8][128];
    __shared__ float Bs[8][128];

    const int tid = threadIdx.x;
    const int tx = tid & 15, ty = tid >> 4;
    const int bm = blockIdx.y, bn = blockIdx.x;

    const int arow = tid >> 1, acol = (tid & 1) * 4;
    const int brow = tid >> 5, bcol = (tid & 31) * 4;
    const float* Aptr = g_att + (size_t)(bm * 128 + arow) * K + acol;
    const float* Bptr = B + (size_t)brow * N + bn * 128 + bcol;

    float acc[8][8];
#pragma unroll
    for (int i = 0; i < 8; i++)
#pragma unroll
        for (int j = 0; j < 8; j++) acc[i][j] = 0.f;

    for (int k0 = 0; k0 < K; k0 += 8) {
        float4 a4 = *(const float4*)(Aptr + k0);
        float4 b4 = *(const float4*)(Bptr + (size_t)k0 * N);
        As[acol + 0][arow] = a4.x;
        As[acol + 1][arow] = a4.y;
        As[acol + 2][arow] = a4.z;
        As[acol + 3][arow] = a4.w;
        *(float4*)&Bs[brow][bcol] = b4;
        __syncthreads();
#pragma unroll
        for (int kk = 0; kk < 8; kk++) {
            float a[8], b[8];
            *(float4*)(&a[0]) = *(const float4*)(&As[kk][ty * 4]);
            *(float4*)(&a[4]) = *(const float4*)(&As[kk][64 + ty * 4]);
            *(float4*)(&b[0]) = *(const float4*)(&Bs[kk][tx * 4]);
            *(float4*)(&b[4]) = *(const float4*)(&Bs[kk][64 + tx * 4]);
#pragma unroll
            for (int i = 0; i < 8; i++)
#pragma unroll
                for (int j = 0; j < 8; j++)
                    acc[i][j] = fmaf(a[i], b[j], acc[i][j]);
        }
        __syncthreads();
    }

#pragma unroll
    for (int i = 0; i < 8; i++) {
        int r  = (i < 4) ? ty * 4 + i : 64 + ty * 4 + (i - 4);
        int gm = bm * 128 + r;
#pragma unroll
        for (int j = 0; j < 8; j++) {
            int c  = (j < 4) ? tx * 4 + j : 64 + tx * 4 + (j - 4);
            int gn = bn * 128 + c;
            out[(size_t)gm * N + gn] = acc[i][j] + bias[gn];
        }
    }
}

// ---------------------------------------------------------------------------
// Flash attention: one block = 64 queries of one (b,h); stream 64-key tiles
// with online softmax. fp32 accumulators in registers (4x4 per thread).
// ---------------------------------------------------------------------------
#define SPAD 65   // odd stride: conflict-free K-reads in the S-GEMM
#define ATTN_SMEM_FLOATS (3 * 64 * SPAD + 64 * 64 + 3 * 64)
#define ATTN_SMEM_BYTES  (ATTN_SMEM_FLOATS * 4)

__global__ __launch_bounds__(256) void attn_kernel()
{
    extern __shared__ float sm[];
    float* Qs   = sm;                     // 64 x SPAD (pre-scaled by 1/8)
    float* Ks   = Qs + 64 * SPAD;         // 64 x SPAD
    float* Ss   = Ks + 64 * SPAD;         // 64 x SPAD (scores -> probs)
    float* Vs   = Ss + 64 * SPAD;         // 64 x 64 (float4-friendly)
    float* mrow = Vs + 64 * 64;           // 64
    float* lrow = mrow + 64;              // 64
    float* crow = lrow + 64;              // 64

    const int tid = threadIdx.x;
    const int tx = tid & 15, ty = tid >> 4;
    const int qt = blockIdx.x;            // query tile 0..31
    const int bh = blockIdx.y;            // 0..63

    const float* qbase = g_q + (size_t)(bh * SEQ + qt * 64) * HS;
    const float* kbase = g_k + (size_t)bh * SEQ * HS;
    const float* vbase = g_v + (size_t)bh * SEQ * HS;

    // Q tile, pre-scaled by 1/sqrt(HS)
    for (int i = tid * 4; i < 64 * HS; i += 256 * 4) {
        int r = i >> 6, d = i & 63;
        float4 q4 = *(const float4*)(qbase + r * HS + d);
        Qs[r * SPAD + d + 0] = q4.x * 0.125f;
        Qs[r * SPAD + d + 1] = q4.y * 0.125f;
        Qs[r * SPAD + d + 2] = q4.z * 0.125f;
        Qs[r * SPAD + d + 3] = q4.w * 0.125f;
    }
    if (tid < 64) { mrow[tid] = -1e30f; lrow[tid] = 0.f; }

    float O[16];
#pragma unroll
    for (int i = 0; i < 16; i++) O[i] = 0.f;
    __syncthreads();

    for (int kt = 0; kt < SEQ / 64; kt++) {
        const float* kb = kbase + (size_t)kt * 64 * HS;
        const float* vb = vbase + (size_t)kt * 64 * HS;
        for (int i = tid * 4; i < 64 * HS; i += 256 * 4) {
            int r = i >> 6, d = i & 63;
            float4 k4 = *(const float4*)(kb + r * HS + d);
            Ks[r * SPAD + d + 0] = k4.x;
            Ks[r * SPAD + d + 1] = k4.y;
            Ks[r * SPAD + d + 2] = k4.z;
            Ks[r * SPAD + d + 3] = k4.w;
            float4 v4 = *(const float4*)(vb + r * HS + d);
            *(float4*)&Vs[r * HS + d] = v4;
        }
        __syncthreads();

        // S = Q @ K^T (64x64), thread computes 4x4
        float acc[16];
#pragma unroll
        for (int i = 0; i < 16; i++) acc[i] = 0.f;
#pragma unroll 4
        for (int d = 0; d < HS; d++) {
            float a0 = Qs[(ty * 4 + 0) * SPAD + d];
            float a1 = Qs[(ty * 4 + 1) * SPAD + d];
            float a2 = Qs[(ty * 4 + 2) * SPAD + d];
            float a3 = Qs[(ty * 4 + 3) * SPAD + d];
            float b0 = Ks[(tx * 4 + 0) * SPAD + d];
            float b1 = Ks[(tx * 4 + 1) * SPAD + d];
            float b2 = Ks[(tx * 4 + 2) * SPAD + d];
            float b3 = Ks[(tx * 4 + 3) * SPAD + d];
            acc[0]  = fmaf(a0, b0, acc[0]);  acc[1]  = fmaf(a0, b1, acc[1]);
            acc[2]  = fmaf(a0, b2, acc[2]);  acc[3]  = fmaf(a0, b3, acc[3]);
            acc[4]  = fmaf(a1, b0, acc[4]);  acc[5]  = fmaf(a1, b1, acc[5]);
            acc[6]  = fmaf(a1, b2, acc[6]);  acc[7]  = fmaf(a1, b3, acc[7]);
            acc[8]  = fmaf(a2, b0, acc[8]);  acc[9]  = fmaf(a2, b1, acc[9]);
            acc[10] = fmaf(a2, b2, acc[10]); acc[11] = fmaf(a2, b3, acc[11]);
            acc[12] = fmaf(a3, b0, acc[12]); acc[13] = fmaf(a3, b1, acc[13]);
            acc[14] = fmaf(a3, b2, acc[14]); acc[15] = fmaf(a3, b3, acc[15]);
        }
#pragma unroll
        for (int i = 0; i < 4; i++)
#pragma unroll
            for (int j = 0; j < 4; j++)
                Ss[(ty * 4 + i) * SPAD + tx * 4 + j] = acc[i * 4 + j];
        __syncthreads();

        // Online softmax: one thread per row
        if (tid < 64) {
            float mold = mrow[tid];
            float mx = mold;
            float* srow = Ss + tid * SPAD;
#pragma unroll 8
            for (int j = 0; j < 64; j++) mx = fmaxf(mx, srow[j]);
            float corr = __expf(mold - mx);
            float sum = 0.f;
#pragma unroll 8
            for (int j = 0; j < 64; j++) {
                float p = __expf(srow[j] - mx);
                srow[j] = p;
                sum += p;
            }
            mrow[tid] = mx;
            lrow[tid] = lrow[tid] * corr + sum;
            crow[tid] = corr;
        }
        __syncthreads();

        // O = O*corr + P @ V
        float c0 = crow[ty * 4 + 0], c1 = crow[ty * 4 + 1];
        float c2 = crow[ty * 4 + 2], c3 = crow[ty * 4 + 3];
#pragma unroll
        for (int j = 0; j < 4; j++) {
            O[0 * 4 + j] *= c0; O[1 * 4 + j] *= c1;
            O[2 * 4 + j] *= c2; O[3 * 4 + j] *= c3;
        }
#pragma unroll 2
        for (int jk = 0; jk < 64; jk++) {
            float p0 = Ss[(ty * 4 + 0) * SPAD + jk];
            float p1 = Ss[(ty * 4 + 1) * SPAD + jk];
            float p2 = Ss[(ty * 4 + 2) * SPAD + jk];
            float p3 = Ss[(ty * 4 + 3) * SPAD + jk];
            float4 v4 = *(const float4*)&Vs[jk * HS + tx * 4];
            O[0]  = fmaf(p0, v4.x, O[0]);  O[1]  = fmaf(p0, v4.y, O[1]);
            O[2]  = fmaf(p0, v4.z, O[2]);  O[3]  = fmaf(p0, v4.w, O[3]);
            O[4]  = fmaf(p1, v4.x, O[4]);  O[5]  = fmaf(p1, v4.y, O[5]);
            O[6]  = fmaf(p1, v4.z, O[6]);  O[7]  = fmaf(p1, v4.w, O[7]);
            O[8]  = fmaf(p2, v4.x, O[8]);  O[9]  = fmaf(p2, v4.y, O[9]);
            O[10] = fmaf(p2, v4.z, O[10]); O[11] = fmaf(p2, v4.w, O[11]);
            O[12] = fmaf(p3, v4.x, O[12]); O[13] = fmaf(p3, v4.y, O[13]);
            O[14] = fmaf(p3, v4.z, O[14]); O[15] = fmaf(p3, v4.w, O[15]);
        }
        __syncthreads();
    }

    // normalize + write [B][T][h*64+d]
    const int bb = bh >> 4, h = bh & (NH - 1);
#pragma unroll
    for (int i = 0; i < 4; i++) {
        int r = ty * 4 + i;
        float inv = 1.f / lrow[r];
        int t = qt * 64 + r;
        float* orow = g_att + (size_t)(bb * SEQ + t) * EMB + h * HS + tx * 4;
        orow[0] = O[i * 4 + 0] * inv;
        orow[1] = O[i * 4 + 1] * inv;
        orow[2] = O[i * 4 + 2] * inv;
        orow[3] = O[i * 4 + 3] * inv;
    }
}

// ---------------------------------------------------------------------------
extern "C" void kernel_launch(void* const* d_in, const int* in_sizes, int n_in,
                              void* d_out, int out_size)
{
    const float* x     = (const float*)d_in[0];
    const float* w_qkv = (const float*)d_in[1];
    const float* b_qkv = (const float*)d_in[2];
    const float* w_out = (const float*)d_in[3];
    const float* b_out = (const float*)d_in[4];
    float* out = (float*)d_out;

    qkv_gemm_kernel<<<dim3(24, 64), 256>>>(x, w_qkv, b_qkv);

    cudaFuncSetAttribute(attn_kernel,
                         cudaFuncAttributeMaxDynamicSharedMemorySize,
                         ATTN_SMEM_BYTES);
    attn_kernel<<<dim3(SEQ / 64, BATCH * NH), 256, ATTN_SMEM_BYTES>>>();

    out_gemm_kernel<<<dim3(8, 64), 256>>>(w_out, b_out, out);
}

// round 7
// speedup vs baseline: 1.2302x; 1.2302x over previous
#include <cuda_runtime.h>
#include <mma.h>

using namespace nvcuda;

#define EMB   1024
#define NH    16
#define HS    64
#define BATCH 4
#define SEQ   2048
#define MROWS (BATCH * SEQ)   // 8192
#define N3    (3 * EMB)       // 3072

// Scratch (allocation-free rule: __device__ globals)
__device__ float qkv_tmp[MROWS * N3];    // [B*T][3C], raw (no bias)
__device__ float g_att[MROWS * EMB];     // [B][T][C] head-concat

// ---------------------------------------------------------------------------
// WMMA TF32 GEMM: C[8192, N] = A[8192, 1024] @ W[1024, N]   (no bias)
// block 128x128, BK=16, 256 threads = 8 warps, warp tile 32x64 (2x4 frags)
// ---------------------------------------------------------------------------
#define ALD 20
#define BLD 136

__global__ __launch_bounds__(256) void wmma_gemm_kernel(
    const float* __restrict__ A, const float* __restrict__ W,
    float* __restrict__ C, int N)
{
    __shared__ float Asm[128 * ALD];   // [row][k], ld=ALD
    __shared__ float Bsm[16 * BLD];    // [k][col], ld=BLD

    const int tid  = threadIdx.x;
    const int warp = tid >> 5;
    const int bm = blockIdx.y, bn = blockIdx.x;
    const int wm = (warp & 3) * 32;     // warp row offset in block tile
    const int wn = (warp >> 2) * 64;    // warp col offset

    // A tile 128x16: 512 float4 chunks, 2 per thread (rows ar, ar+64)
    const int ar = tid >> 2, ak = (tid & 3) * 4;
    // B tile 16x128: 512 chunks, 2 per thread (k rows bk, bk+8)
    const int bk = tid >> 5, bc = (tid & 31) * 4;

    wmma::fragment<wmma::accumulator, 16, 16, 8, float> acc[2][4];
#pragma unroll
    for (int mt = 0; mt < 2; mt++)
#pragma unroll
        for (int nt = 0; nt < 4; nt++)
            wmma::fill_fragment(acc[mt][nt], 0.0f);

    for (int kt = 0; kt < EMB / 16; kt++) {
        // load + convert to tf32-in-float
        const float4 a0 = *(const float4*)(
            A + (size_t)(bm * 128 + ar) * EMB + kt * 16 + ak);
        const float4 a1 = *(const float4*)(
            A + (size_t)(bm * 128 + ar + 64) * EMB + kt * 16 + ak);
        Asm[ar * ALD + ak + 0] = wmma::__float_to_tf32(a0.x);
        Asm[ar * ALD + ak + 1] = wmma::__float_to_tf32(a0.y);
        Asm[ar * ALD + ak + 2] = wmma::__float_to_tf32(a0.z);
        Asm[ar * ALD + ak + 3] = wmma::__float_to_tf32(a0.w);
        Asm[(ar + 64) * ALD + ak + 0] = wmma::__float_to_tf32(a1.x);
        Asm[(ar + 64) * ALD + ak + 1] = wmma::__float_to_tf32(a1.y);
        Asm[(ar + 64) * ALD + ak + 2] = wmma::__float_to_tf32(a1.z);
        Asm[(ar + 64) * ALD + ak + 3] = wmma::__float_to_tf32(a1.w);
        const float4 b0 = *(const float4*)(
            W + (size_t)(kt * 16 + bk) * N + bn * 128 + bc);
        const float4 b1 = *(const float4*)(
            W + (size_t)(kt * 16 + bk + 8) * N + bn * 128 + bc);
        Bsm[bk * BLD + bc + 0] = wmma::__float_to_tf32(b0.x);
        Bsm[bk * BLD + bc + 1] = wmma::__float_to_tf32(b0.y);
        Bsm[bk * BLD + bc + 2] = wmma::__float_to_tf32(b0.z);
        Bsm[bk * BLD + bc + 3] = wmma::__float_to_tf32(b0.w);
        Bsm[(bk + 8) * BLD + bc + 0] = wmma::__float_to_tf32(b1.x);
        Bsm[(bk + 8) * BLD + bc + 1] = wmma::__float_to_tf32(b1.y);
        Bsm[(bk + 8) * BLD + bc + 2] = wmma::__float_to_tf32(b1.z);
        Bsm[(bk + 8) * BLD + bc + 3] = wmma::__float_to_tf32(b1.w);
        __syncthreads();

#pragma unroll
        for (int ks = 0; ks < 2; ks++) {
            wmma::fragment<wmma::matrix_a, 16, 16, 8,
                           wmma::precision::tf32, wmma::row_major> af[2];
            wmma::fragment<wmma::matrix_b, 16, 16, 8,
                           wmma::precision::tf32, wmma::row_major> bf[4];
            wmma::load_matrix_sync(af[0], &Asm[wm * ALD + ks * 8], ALD);
            wmma::load_matrix_sync(af[1], &Asm[(wm + 16) * ALD + ks * 8], ALD);
#pragma unroll
            for (int nt = 0; nt < 4; nt++)
                wmma::load_matrix_sync(bf[nt],
                    &Bsm[ks * 8 * BLD + wn + nt * 16], BLD);
#pragma unroll
            for (int mt = 0; mt < 2; mt++)
#pragma unroll
                for (int nt = 0; nt < 4; nt++)
                    wmma::mma_sync(acc[mt][nt], af[mt], bf[nt], acc[mt][nt]);
        }
        __syncthreads();
    }

#pragma unroll
    for (int mt = 0; mt < 2; mt++)
#pragma unroll
        for (int nt = 0; nt < 4; nt++)
            wmma::store_matrix_sync(
                C + (size_t)(bm * 128 + wm + mt * 16) * N
                  + bn * 128 + wn + nt * 16,
                acc[mt][nt], N, wmma::mem_row_major);
}

// ---------------------------------------------------------------------------
// Bias add for the output projection: out[r][c] += bias[c]
// ---------------------------------------------------------------------------
__global__ __launch_bounds__(256) void bias_out_kernel(
    float* __restrict__ out, const float* __restrict__ bias)
{
    const int i = (blockIdx.x * 256 + threadIdx.x) * 4;
    float4 v = *(float4*)(out + i);
    const float4 b = *(const float4*)(bias + (i & (EMB - 1)));
    v.x += b.x; v.y += b.y; v.z += b.z; v.w += b.w;
    *(float4*)(out + i) = v;
}

// ---------------------------------------------------------------------------
// Flash attention (fp32 SIMT, structure identical to the passing Round-1
// kernel). Reads qkv_tmp directly (strided) and folds the qkv bias into the
// smem fill. One block = 64 queries of one (b,h); 64-key tiles, online
// softmax.
// ---------------------------------------------------------------------------
#define SPAD 65
#define ATTN_SMEM_FLOATS (3 * 64 * SPAD + 64 * 64 + 3 * 64)
#define ATTN_SMEM_BYTES  (ATTN_SMEM_FLOATS * 4)

__global__ __launch_bounds__(256) void attn_kernel(
    const float* __restrict__ b_qkv)
{
    extern __shared__ float sm[];
    float* Qs   = sm;                     // 64 x SPAD (pre-scaled by 1/8)
    float* Ks   = Qs + 64 * SPAD;         // 64 x SPAD
    float* Ss   = Ks + 64 * SPAD;         // 64 x SPAD (scores -> probs)
    float* Vs   = Ss + 64 * SPAD;         // 64 x 64
    float* mrow = Vs + 64 * 64;           // 64
    float* lrow = mrow + 64;              // 64
    float* crow = lrow + 64;              // 64

    const int tid = threadIdx.x;
    const int tx = tid & 15, ty = tid >> 4;
    const int qt = blockIdx.x;            // query tile 0..31
    const int bh = blockIdx.y;            // 0..63
    const int bb = bh >> 4, h = bh & (NH - 1);

    const size_t rowbase = (size_t)bb * SEQ;   // row of qkv_tmp for t=0
    const int qcol = h * HS;
    const int kcol = EMB + h * HS;
    const int vcol = 2 * EMB + h * HS;

    // Q tile: (q + bias) * 0.125
    for (int i = tid * 4; i < 64 * HS; i += 256 * 4) {
        const int r = i >> 6, d = i & 63;
        const float4 q4 = *(const float4*)(
            qkv_tmp + (rowbase + qt * 64 + r) * N3 + qcol + d);
        const float4 bq = *(const float4*)(b_qkv + qcol + d);
        Qs[r * SPAD + d + 0] = (q4.x + bq.x) * 0.125f;
        Qs[r * SPAD + d + 1] = (q4.y + bq.y) * 0.125f;
        Qs[r * SPAD + d + 2] = (q4.z + bq.z) * 0.125f;
        Qs[r * SPAD + d + 3] = (q4.w + bq.w) * 0.125f;
    }
    if (tid < 64) { mrow[tid] = -1e30f; lrow[tid] = 0.f; }

    float O[16];
#pragma unroll
    for (int i = 0; i < 16; i++) O[i] = 0.f;
    __syncthreads();

    for (int kt = 0; kt < SEQ / 64; kt++) {
        for (int i = tid * 4; i < 64 * HS; i += 256 * 4) {
            const int r = i >> 6, d = i & 63;
            const size_t row = rowbase + kt * 64 + r;
            const float4 k4 = *(const float4*)(
                qkv_tmp + row * N3 + kcol + d);
            const float4 bk = *(const float4*)(b_qkv + kcol + d);
            Ks[r * SPAD + d + 0] = k4.x + bk.x;
            Ks[r * SPAD + d + 1] = k4.y + bk.y;
            Ks[r * SPAD + d + 2] = k4.z + bk.z;
            Ks[r * SPAD + d + 3] = k4.w + bk.w;
            const float4 v4 = *(const float4*)(
                qkv_tmp + row * N3 + vcol + d);
            const float4 bv = *(const float4*)(b_qkv + vcol + d);
            Vs[r * HS + d + 0] = v4.x + bv.x;
            Vs[r * HS + d + 1] = v4.y + bv.y;
            Vs[r * HS + d + 2] = v4.z + bv.z;
            Vs[r * HS + d + 3] = v4.w + bv.w;
        }
        __syncthreads();

        float acc[16];
#pragma unroll
        for (int i = 0; i < 16; i++) acc[i] = 0.f;
#pragma unroll 4
        for (int d = 0; d < HS; d++) {
            float a0 = Qs[(ty * 4 + 0) * SPAD + d];
            float a1 = Qs[(ty * 4 + 1) * SPAD + d];
            float a2 = Qs[(ty * 4 + 2) * SPAD + d];
            float a3 = Qs[(ty * 4 + 3) * SPAD + d];
            float b0 = Ks[(tx * 4 + 0) * SPAD + d];
            float b1 = Ks[(tx * 4 + 1) * SPAD + d];
            float b2 = Ks[(tx * 4 + 2) * SPAD + d];
            float b3 = Ks[(tx * 4 + 3) * SPAD + d];
            acc[0]  = fmaf(a0, b0, acc[0]);  acc[1]  = fmaf(a0, b1, acc[1]);
            acc[2]  = fmaf(a0, b2, acc[2]);  acc[3]  = fmaf(a0, b3, acc[3]);
            acc[4]  = fmaf(a1, b0, acc[4]);  acc[5]  = fmaf(a1, b1, acc[5]);
            acc[6]  = fmaf(a1, b2, acc[6]);  acc[7]  = fmaf(a1, b3, acc[7]);
            acc[8]  = fmaf(a2, b0, acc[8]);  acc[9]  = fmaf(a2, b1, acc[9]);
            acc[10] = fmaf(a2, b2, acc[10]); acc[11] = fmaf(a2, b3, acc[11]);
            acc[12] = fmaf(a3, b0, acc[12]); acc[13] = fmaf(a3, b1, acc[13]);
            acc[14] = fmaf(a3, b2, acc[14]); acc[15] = fmaf(a3, b3, acc[15]);
        }
#pragma unroll
        for (int i = 0; i < 4; i++)
#pragma unroll
            for (int j = 0; j < 4; j++)
                Ss[(ty * 4 + i) * SPAD + tx * 4 + j] = acc[i * 4 + j];
        __syncthreads();

        if (tid < 64) {
            float mold = mrow[tid];
            float mx = mold;
            float* srow = Ss + tid * SPAD;
#pragma unroll 8
            for (int j = 0; j < 64; j++) mx = fmaxf(mx, srow[j]);
            float corr = __expf(mold - mx);
            float sum = 0.f;
#pragma unroll 8
            for (int j = 0; j < 64; j++) {
                float p = __expf(srow[j] - mx);
                srow[j] = p;
                sum += p;
            }
            mrow[tid] = mx;
            lrow[tid] = lrow[tid] * corr + sum;
            crow[tid] = corr;
        }
        __syncthreads();

        float c0 = crow[ty * 4 + 0], c1 = crow[ty * 4 + 1];
        float c2 = crow[ty * 4 + 2], c3 = crow[ty * 4 + 3];
#pragma unroll
        for (int j = 0; j < 4; j++) {
            O[0 * 4 + j] *= c0; O[1 * 4 + j] *= c1;
            O[2 * 4 + j] *= c2; O[3 * 4 + j] *= c3;
        }
#pragma unroll 2
        for (int jk = 0; jk < 64; jk++) {
            float p0 = Ss[(ty * 4 + 0) * SPAD + jk];
            float p1 = Ss[(ty * 4 + 1) * SPAD + jk];
            float p2 = Ss[(ty * 4 + 2) * SPAD + jk];
            float p3 = Ss[(ty * 4 + 3) * SPAD + jk];
            float4 v4 = *(const float4*)&Vs[jk * HS + tx * 4];
            O[0]  = fmaf(p0, v4.x, O[0]);  O[1]  = fmaf(p0, v4.y, O[1]);
            O[2]  = fmaf(p0, v4.z, O[2]);  O[3]  = fmaf(p0, v4.w, O[3]);
            O[4]  = fmaf(p1, v4.x, O[4]);  O[5]  = fmaf(p1, v4.y, O[5]);
            O[6]  = fmaf(p1, v4.z, O[6]);  O[7]  = fmaf(p1, v4.w, O[7]);
            O[8]  = fmaf(p2, v4.x, O[8]);  O[9]  = fmaf(p2, v4.y, O[9]);
            O[10] = fmaf(p2, v4.z, O[10]); O[11] = fmaf(p2, v4.w, O[11]);
            O[12] = fmaf(p3, v4.x, O[12]); O[13] = fmaf(p3, v4.y, O[13]);
            O[14] = fmaf(p3, v4.z, O[14]); O[15] = fmaf(p3, v4.w, O[15]);
        }
        __syncthreads();
    }

    // normalize + write [B][T][h*64+d]
#pragma unroll
    for (int i = 0; i < 4; i++) {
        int r = ty * 4 + i;
        float inv = 1.f / lrow[r];
        int t = qt * 64 + r;
        float* orow = g_att + (size_t)(bb * SEQ + t) * EMB + h * HS + tx * 4;
        orow[0] = O[i * 4 + 0] * inv;
        orow[1] = O[i * 4 + 1] * inv;
        orow[2] = O[i * 4 + 2] * inv;
        orow[3] = O[i * 4 + 3] * inv;
    }
}

// ---------------------------------------------------------------------------
extern "C" void kernel_launch(void* const* d_in, const int* in_sizes, int n_in,
                              void* d_out, int out_size)
{
    const float* x     = (const float*)d_in[0];
    const float* w_qkv = (const float*)d_in[1];
    const float* b_qkv = (const float*)d_in[2];
    const float* w_out = (const float*)d_in[3];
    const float* b_out = (const float*)d_in[4];
    float* out = (float*)d_out;

    float* qkv_ptr = nullptr;
    float* att_ptr = nullptr;
    cudaGetSymbolAddress((void**)&qkv_ptr, qkv_tmp);
    cudaGetSymbolAddress((void**)&att_ptr, g_att);

    // QKV projection (raw, bias folded into attention load)
    wmma_gemm_kernel<<<dim3(N3 / 128, MROWS / 128), 256>>>(
        x, w_qkv, qkv_ptr, N3);

    cudaFuncSetAttribute(attn_kernel,
                         cudaFuncAttributeMaxDynamicSharedMemorySize,
                         ATTN_SMEM_BYTES);
    attn_kernel<<<dim3(SEQ / 64, BATCH * NH), 256, ATTN_SMEM_BYTES>>>(b_qkv);

    // Output projection (raw) + bias
    wmma_gemm_kernel<<<dim3(EMB / 128, MROWS / 128), 256>>>(
        att_ptr, w_out, out, EMB);
    bias_out_kernel<<<(MROWS * EMB) / (256 * 4), 256>>>(out, b_out);
}

// round 9
// speedup vs baseline: 1.2512x; 1.0171x over previous
#include <cuda_runtime.h>
#include <mma.h>

using namespace nvcuda;

#define EMB   1024
#define NH    16
#define HS    64
#define BATCH 4
#define SEQ   2048
#define MROWS (BATCH * SEQ)   // 8192
#define N3    (3 * EMB)       // 3072

// Scratch (allocation-free rule: __device__ globals)
__device__ float qkv_tmp[MROWS * N3];    // [B*T][3C], raw (no bias)
__device__ float g_att[MROWS * EMB];     // [B][T][C] head-concat

// ---------------------------------------------------------------------------
// WMMA TF32 GEMM: C[8192, N] = A[8192, 1024] @ W[1024, N]   (no bias)
// block 128x128, BK=16, 256 threads = 8 warps, warp tile 32x64 (2x4 frags)
// (unchanged from the passing Round-7 kernel)
// ---------------------------------------------------------------------------
#define ALD 20
#define BLD 136

__global__ __launch_bounds__(256) void wmma_gemm_kernel(
    const float* __restrict__ A, const float* __restrict__ W,
    float* __restrict__ C, int N)
{
    __shared__ float Asm[128 * ALD];   // [row][k], ld=ALD
    __shared__ float Bsm[16 * BLD];    // [k][col], ld=BLD

    const int tid  = threadIdx.x;
    const int warp = tid >> 5;
    const int bm = blockIdx.y, bn = blockIdx.x;
    const int wm = (warp & 3) * 32;
    const int wn = (warp >> 2) * 64;

    const int ar = tid >> 2, ak = (tid & 3) * 4;
    const int bk = tid >> 5, bc = (tid & 31) * 4;

    wmma::fragment<wmma::accumulator, 16, 16, 8, float> acc[2][4];
#pragma unroll
    for (int mt = 0; mt < 2; mt++)
#pragma unroll
        for (int nt = 0; nt < 4; nt++)
            wmma::fill_fragment(acc[mt][nt], 0.0f);

    for (int kt = 0; kt < EMB / 16; kt++) {
        const float4 a0 = *(const float4*)(
            A + (size_t)(bm * 128 + ar) * EMB + kt * 16 + ak);
        const float4 a1 = *(const float4*)(
            A + (size_t)(bm * 128 + ar + 64) * EMB + kt * 16 + ak);
        Asm[ar * ALD + ak + 0] = wmma::__float_to_tf32(a0.x);
        Asm[ar * ALD + ak + 1] = wmma::__float_to_tf32(a0.y);
        Asm[ar * ALD + ak + 2] = wmma::__float_to_tf32(a0.z);
        Asm[ar * ALD + ak + 3] = wmma::__float_to_tf32(a0.w);
        Asm[(ar + 64) * ALD + ak + 0] = wmma::__float_to_tf32(a1.x);
        Asm[(ar + 64) * ALD + ak + 1] = wmma::__float_to_tf32(a1.y);
        Asm[(ar + 64) * ALD + ak + 2] = wmma::__float_to_tf32(a1.z);
        Asm[(ar + 64) * ALD + ak + 3] = wmma::__float_to_tf32(a1.w);
        const float4 b0 = *(const float4*)(
            W + (size_t)(kt * 16 + bk) * N + bn * 128 + bc);
        const float4 b1 = *(const float4*)(
            W + (size_t)(kt * 16 + bk + 8) * N + bn * 128 + bc);
        Bsm[bk * BLD + bc + 0] = wmma::__float_to_tf32(b0.x);
        Bsm[bk * BLD + bc + 1] = wmma::__float_to_tf32(b0.y);
        Bsm[bk * BLD + bc + 2] = wmma::__float_to_tf32(b0.z);
        Bsm[bk * BLD + bc + 3] = wmma::__float_to_tf32(b0.w);
        Bsm[(bk + 8) * BLD + bc + 0] = wmma::__float_to_tf32(b1.x);
        Bsm[(bk + 8) * BLD + bc + 1] = wmma::__float_to_tf32(b1.y);
        Bsm[(bk + 8) * BLD + bc + 2] = wmma::__float_to_tf32(b1.z);
        Bsm[(bk + 8) * BLD + bc + 3] = wmma::__float_to_tf32(b1.w);
        __syncthreads();

#pragma unroll
        for (int ks = 0; ks < 2; ks++) {
            wmma::fragment<wmma::matrix_a, 16, 16, 8,
                           wmma::precision::tf32, wmma::row_major> af[2];
            wmma::fragment<wmma::matrix_b, 16, 16, 8,
                           wmma::precision::tf32, wmma::row_major> bf[4];
            wmma::load_matrix_sync(af[0], &Asm[wm * ALD + ks * 8], ALD);
            wmma::load_matrix_sync(af[1], &Asm[(wm + 16) * ALD + ks * 8], ALD);
#pragma unroll
            for (int nt = 0; nt < 4; nt++)
                wmma::load_matrix_sync(bf[nt],
                    &Bsm[ks * 8 * BLD + wn + nt * 16], BLD);
#pragma unroll
            for (int mt = 0; mt < 2; mt++)
#pragma unroll
                for (int nt = 0; nt < 4; nt++)
                    wmma::mma_sync(acc[mt][nt], af[mt], bf[nt], acc[mt][nt]);
        }
        __syncthreads();
    }

#pragma unroll
    for (int mt = 0; mt < 2; mt++)
#pragma unroll
        for (int nt = 0; nt < 4; nt++)
            wmma::store_matrix_sync(
                C + (size_t)(bm * 128 + wm + mt * 16) * N
                  + bn * 128 + wn + nt * 16,
                acc[mt][nt], N, wmma::mem_row_major);
}

// ---------------------------------------------------------------------------
// Bias add for the output projection: out[r][c] += bias[c]
// ---------------------------------------------------------------------------
__global__ __launch_bounds__(256) void bias_out_kernel(
    float* __restrict__ out, const float* __restrict__ bias)
{
    const int i = (blockIdx.x * 256 + threadIdx.x) * 4;
    float4 v = *(float4*)(out + i);
    const float4 b = *(const float4*)(bias + (i & (EMB - 1)));
    v.x += b.x; v.y += b.y; v.z += b.z; v.w += b.w;
    *(float4*)(out + i) = v;
}

// ---------------------------------------------------------------------------
// WMMA TF32 flash attention.
// Block = 128 queries of one (b,h), 256 threads = 8 warps, warp owns 16 rows.
// 64-key tiles. Online softmax: 2 lanes per row, stats in registers.
// O kept in smem (wmma accumulator layout is opaque); PV stored to the freed
// P region each tile, then O = O*corr + PV per lane.
// One __syncthreads per tile (K/V reload). Bias folded at load.
// ---------------------------------------------------------------------------
#define LDS68 68
#define AT_Q  0
#define AT_K  (128 * LDS68)
#define AT_V  (AT_K + 64 * LDS68)
#define AT_P  (AT_V + 64 * LDS68)
#define AT_O  (AT_P + 128 * LDS68)
#define ATTN_SMEM_FLOATS (AT_O + 128 * LDS68)
#define ATTN_SMEM_BYTES  (ATTN_SMEM_FLOATS * 4)

__global__ __launch_bounds__(256) void attn_wmma_kernel(
    const float* __restrict__ b_qkv)
{
    extern __shared__ float sm[];
    float* Qs = sm + AT_Q;     // [128][68] tf32, pre-scaled
    float* Ks = sm + AT_K;     // [64][68]  tf32
    float* Vs = sm + AT_V;     // [64][68]  tf32
    float* Ps = sm + AT_P;     // [128][68] S (fp32) -> P (tf32) -> PV (fp32)
    float* Os = sm + AT_O;     // [128][68] fp32 running O

    const int tid  = threadIdx.x;
    const int lane = tid & 31, warp = tid >> 5;
    const int qb = warp * 16;            // warp's query-row base
    const int rowIdx = lane >> 1, half = lane & 1;
    const int r = qb + rowIdx;           // this lane's row
    const int rbase = r * LDS68 + half * 32;

    const int qt = blockIdx.x;           // 0..15
    const int bh = blockIdx.y;           // 0..63
    const int bb = bh >> 4, h = bh & (NH - 1);
    const size_t rowbase = (size_t)bb * SEQ;
    const int qcol = h * HS, kcol = EMB + h * HS, vcol = 2 * EMB + h * HS;

    // load Q tile (scaled 1/8, +bias, tf32)
    for (int i = tid * 4; i < 128 * HS; i += 256 * 4) {
        const int rr = i >> 6, d = i & 63;
        const float4 q4 = *(const float4*)(
            qkv_tmp + (rowbase + qt * 128 + rr) * N3 + qcol + d);
        const float4 bq = *(const float4*)(b_qkv + qcol + d);
        Qs[rr * LDS68 + d + 0] = wmma::__float_to_tf32((q4.x + bq.x) * 0.125f);
        Qs[rr * LDS68 + d + 1] = wmma::__float_to_tf32((q4.y + bq.y) * 0.125f);
        Qs[rr * LDS68 + d + 2] = wmma::__float_to_tf32((q4.z + bq.z) * 0.125f);
        Qs[rr * LDS68 + d + 3] = wmma::__float_to_tf32((q4.w + bq.w) * 0.125f);
    }
    // zero O
    for (int i = tid; i < 128 * LDS68; i += 256) Os[i] = 0.f;

    float mReg = -1e30f, lReg = 0.f;
    __syncthreads();

    for (int kt = 0; kt < SEQ / 64; kt++) {
        // K/V tile (+bias, tf32)
        for (int i = tid * 4; i < 64 * HS; i += 256 * 4) {
            const int rr = i >> 6, d = i & 63;
            const size_t grow = rowbase + kt * 64 + rr;
            const float4 k4 = *(const float4*)(qkv_tmp + grow * N3 + kcol + d);
            const float4 bk = *(const float4*)(b_qkv + kcol + d);
            Ks[rr * LDS68 + d + 0] = wmma::__float_to_tf32(k4.x + bk.x);
            Ks[rr * LDS68 + d + 1] = wmma::__float_to_tf32(k4.y + bk.y);
            Ks[rr * LDS68 + d + 2] = wmma::__float_to_tf32(k4.z + bk.z);
            Ks[rr * LDS68 + d + 3] = wmma::__float_to_tf32(k4.w + bk.w);
            const float4 v4 = *(const float4*)(qkv_tmp + grow * N3 + vcol + d);
            const float4 bv = *(const float4*)(b_qkv + vcol + d);
            Vs[rr * LDS68 + d + 0] = wmma::__float_to_tf32(v4.x + bv.x);
            Vs[rr * LDS68 + d + 1] = wmma::__float_to_tf32(v4.y + bv.y);
            Vs[rr * LDS68 + d + 2] = wmma::__float_to_tf32(v4.z + bv.z);
            Vs[rr * LDS68 + d + 3] = wmma::__float_to_tf32(v4.w + bv.w);
        }
        __syncthreads();

        // ---- S = Q @ K^T  (warp: 16 x 64) ----
        {
            wmma::fragment<wmma::accumulator, 16, 16, 8, float> sacc[4];
#pragma unroll
            for (int nt = 0; nt < 4; nt++) wmma::fill_fragment(sacc[nt], 0.0f);
#pragma unroll
            for (int d0 = 0; d0 < HS; d0 += 8) {
                wmma::fragment<wmma::matrix_a, 16, 16, 8,
                               wmma::precision::tf32, wmma::row_major> af;
                wmma::load_matrix_sync(af, &Qs[qb * LDS68 + d0], LDS68);
#pragma unroll
                for (int nt = 0; nt < 4; nt++) {
                    wmma::fragment<wmma::matrix_b, 16, 16, 8,
                                   wmma::precision::tf32, wmma::col_major> bf;
                    wmma::load_matrix_sync(bf,
                        &Ks[(nt * 16) * LDS68 + d0], LDS68);
                    wmma::mma_sync(sacc[nt], af, bf, sacc[nt]);
                }
            }
#pragma unroll
            for (int nt = 0; nt < 4; nt++)
                wmma::store_matrix_sync(&Ps[qb * LDS68 + nt * 16],
                                        sacc[nt], LDS68, wmma::mem_row_major);
        }

        // ---- online softmax (2 lanes per row, stats in registers) ----
        float corr;
        {
            float mx = -1e30f;
#pragma unroll
            for (int j = 0; j < 32; j += 4) {
                const float4 v = *(const float4*)&Ps[rbase + j];
                mx = fmaxf(mx, fmaxf(fmaxf(v.x, v.y), fmaxf(v.z, v.w)));
            }
            mx = fmaxf(mx, __shfl_xor_sync(0xffffffff, mx, 1));
            const float mn = fmaxf(mReg, mx);
            corr = __expf(mReg - mn);
            mReg = mn;
            float sum = 0.f;
#pragma unroll
            for (int j = 0; j < 32; j += 4) {
                float4 v = *(const float4*)&Ps[rbase + j];
                v.x = __expf(v.x - mn); v.y = __expf(v.y - mn);
                v.z = __expf(v.z - mn); v.w = __expf(v.w - mn);
                sum += v.x + v.y + v.z + v.w;
                float4 t;
                t.x = wmma::__float_to_tf32(v.x);
                t.y = wmma::__float_to_tf32(v.y);
                t.z = wmma::__float_to_tf32(v.z);
                t.w = wmma::__float_to_tf32(v.w);
                *(float4*)&Ps[rbase + j] = t;
            }
            sum += __shfl_xor_sync(0xffffffff, sum, 1);
            lReg = lReg * corr + sum;
        }
        __syncwarp();

        // ---- PV = P @ V  (warp: 16 x 64) ----
        {
            wmma::fragment<wmma::accumulator, 16, 16, 8, float> pv[4];
#pragma unroll
            for (int nt = 0; nt < 4; nt++) wmma::fill_fragment(pv[nt], 0.0f);
#pragma unroll
            for (int kk = 0; kk < 64; kk += 8) {
                wmma::fragment<wmma::matrix_a, 16, 16, 8,
                               wmma::precision::tf32, wmma::row_major> af;
                wmma::load_matrix_sync(af, &Ps[qb * LDS68 + kk], LDS68);
#pragma unroll
                for (int nt = 0; nt < 4; nt++) {
                    wmma::fragment<wmma::matrix_b, 16, 16, 8,
                                   wmma::precision::tf32, wmma::row_major> bf;
                    wmma::load_matrix_sync(bf,
                        &Vs[kk * LDS68 + nt * 16], LDS68);
                    wmma::mma_sync(pv[nt], af, bf, pv[nt]);
                }
            }
            __syncwarp();   // all lanes done reading P before overwrite
#pragma unroll
            for (int nt = 0; nt < 4; nt++)
                wmma::store_matrix_sync(&Ps[qb * LDS68 + nt * 16],
                                        pv[nt], LDS68, wmma::mem_row_major);
        }
        __syncwarp();

        // ---- O = O*corr + PV  (lane owns half of its row) ----
#pragma unroll
        for (int j = 0; j < 32; j += 4) {
            float4 o4 = *(const float4*)&Os[rbase + j];
            const float4 p4 = *(const float4*)&Ps[rbase + j];
            o4.x = fmaf(o4.x, corr, p4.x);
            o4.y = fmaf(o4.y, corr, p4.y);
            o4.z = fmaf(o4.z, corr, p4.z);
            o4.w = fmaf(o4.w, corr, p4.w);
            *(float4*)&Os[rbase + j] = o4;
        }
        __syncthreads();    // before K/V reload
    }

    // normalize + write [B][T][h*64+d]
    const float inv = 1.f / lReg;
    float* orow = g_att + (size_t)(rowbase + qt * 128 + r) * EMB
                  + h * HS + half * 32;
#pragma unroll
    for (int j = 0; j < 32; j += 4) {
        const float4 o4 = *(const float4*)&Os[rbase + j];
        *(float4*)&orow[j] = make_float4(o4.x * inv, o4.y * inv,
                                         o4.z * inv, o4.w * inv);
    }
}

// ---------------------------------------------------------------------------
extern "C" void kernel_launch(void* const* d_in, const int* in_sizes, int n_in,
                              void* d_out, int out_size)
{
    const float* x     = (const float*)d_in[0];
    const float* w_qkv = (const float*)d_in[1];
    const float* b_qkv = (const float*)d_in[2];
    const float* w_out = (const float*)d_in[3];
    const float* b_out = (const float*)d_in[4];
    float* out = (float*)d_out;

    float* qkv_ptr = nullptr;
    float* att_ptr = nullptr;
    cudaGetSymbolAddress((void**)&qkv_ptr, qkv_tmp);
    cudaGetSymbolAddress((void**)&att_ptr, g_att);

    // QKV projection (raw, bias folded into attention load)
    wmma_gemm_kernel<<<dim3(N3 / 128, MROWS / 128), 256>>>(
        x, w_qkv, qkv_ptr, N3);

    cudaFuncSetAttribute(attn_wmma_kernel,
                         cudaFuncAttributeMaxDynamicSharedMemorySize,
                         ATTN_SMEM_BYTES);
    attn_wmma_kernel<<<dim3(SEQ / 128, BATCH * NH), 256, ATTN_SMEM_BYTES>>>(
        b_qkv);

    // Output projection (raw) + bias
    wmma_gemm_kernel<<<dim3(EMB / 128, MROWS / 128), 256>>>(
        att_ptr, w_out, out, EMB);
    bias_out_kernel<<<(MROWS * EMB) / (256 * 4), 256>>>(out, b_out);
}

// round 10
// speedup vs baseline: 1.2737x; 1.0180x over previous
#include <cuda_runtime.h>
#include <mma.h>

using namespace nvcuda;

#define EMB   1024
#define NH    16
#define HS    64
#define BATCH 4
#define SEQ   2048
#define MROWS (BATCH * SEQ)   // 8192
#define N3    (3 * EMB)       // 3072

// Scratch (allocation-free rule: __device__ globals)
__device__ float qkv_tmp[MROWS * N3];    // [B*T][3C], raw (no bias)
__device__ float g_att[MROWS * EMB];     // [B][T][C] head-concat

// ---------------------------------------------------------------------------
// WMMA TF32 GEMM: C[8192, N] = A[8192, 1024] @ W[1024, N]   (no bias)
// block 128x128, BK=16, 256 threads = 8 warps, warp tile 32x64 (2x4 frags)
// Double-buffered smem, register-staged prefetch, ONE sync per k-tile.
// ---------------------------------------------------------------------------
#define ALD 20
#define BLD 136

__global__ __launch_bounds__(256) void wmma_gemm_kernel(
    const float* __restrict__ A, const float* __restrict__ W,
    float* __restrict__ C, int N)
{
    __shared__ float Asm[2][128 * ALD];
    __shared__ float Bsm[2][16 * BLD];

    const int tid  = threadIdx.x;
    const int warp = tid >> 5;
    const int bm = blockIdx.y, bn = blockIdx.x;
    const int wm = (warp & 3) * 32;
    const int wn = (warp >> 2) * 64;

    const int ar = tid >> 2, ak = (tid & 3) * 4;
    const int bk = tid >> 5, bc = (tid & 31) * 4;

    const float* ApG0 = A + (size_t)(bm * 128 + ar) * EMB + ak;
    const float* ApG1 = A + (size_t)(bm * 128 + ar + 64) * EMB + ak;
    const float* BpG0 = W + (size_t)bk * N + bn * 128 + bc;
    const float* BpG1 = W + (size_t)(bk + 8) * N + bn * 128 + bc;

    wmma::fragment<wmma::accumulator, 16, 16, 8, float> acc[2][4];
#pragma unroll
    for (int mt = 0; mt < 2; mt++)
#pragma unroll
        for (int nt = 0; nt < 4; nt++)
            wmma::fill_fragment(acc[mt][nt], 0.0f);

    // prologue: tile 0 -> buf 0
    {
        const float4 a0 = *(const float4*)(ApG0);
        const float4 a1 = *(const float4*)(ApG1);
        const float4 b0 = *(const float4*)(BpG0);
        const float4 b1 = *(const float4*)(BpG1);
        float* As = Asm[0];
        float* Bs = Bsm[0];
        As[ar * ALD + ak + 0] = wmma::__float_to_tf32(a0.x);
        As[ar * ALD + ak + 1] = wmma::__float_to_tf32(a0.y);
        As[ar * ALD + ak + 2] = wmma::__float_to_tf32(a0.z);
        As[ar * ALD + ak + 3] = wmma::__float_to_tf32(a0.w);
        As[(ar + 64) * ALD + ak + 0] = wmma::__float_to_tf32(a1.x);
        As[(ar + 64) * ALD + ak + 1] = wmma::__float_to_tf32(a1.y);
        As[(ar + 64) * ALD + ak + 2] = wmma::__float_to_tf32(a1.z);
        As[(ar + 64) * ALD + ak + 3] = wmma::__float_to_tf32(a1.w);
        Bs[bk * BLD + bc + 0] = wmma::__float_to_tf32(b0.x);
        Bs[bk * BLD + bc + 1] = wmma::__float_to_tf32(b0.y);
        Bs[bk * BLD + bc + 2] = wmma::__float_to_tf32(b0.z);
        Bs[bk * BLD + bc + 3] = wmma::__float_to_tf32(b0.w);
        Bs[(bk + 8) * BLD + bc + 0] = wmma::__float_to_tf32(b1.x);
        Bs[(bk + 8) * BLD + bc + 1] = wmma::__float_to_tf32(b1.y);
        Bs[(bk + 8) * BLD + bc + 2] = wmma::__float_to_tf32(b1.z);
        Bs[(bk + 8) * BLD + bc + 3] = wmma::__float_to_tf32(b1.w);
    }
    __syncthreads();

    const int NK = EMB / 16;   // 64
    for (int kt = 0; kt < NK; kt++) {
        float4 a0, a1, b0, b1;
        const bool more = (kt + 1 < NK);
        if (more) {
            const int ko = (kt + 1) * 16;
            a0 = *(const float4*)(ApG0 + ko);
            a1 = *(const float4*)(ApG1 + ko);
            b0 = *(const float4*)(BpG0 + (size_t)ko * N);
            b1 = *(const float4*)(BpG1 + (size_t)ko * N);
        }

        const float* As = Asm[kt & 1];
        const float* Bs = Bsm[kt & 1];
#pragma unroll
        for (int ks = 0; ks < 2; ks++) {
            wmma::fragment<wmma::matrix_a, 16, 16, 8,
                           wmma::precision::tf32, wmma::row_major> af[2];
            wmma::fragment<wmma::matrix_b, 16, 16, 8,
                           wmma::precision::tf32, wmma::row_major> bf[4];
            wmma::load_matrix_sync(af[0], &As[wm * ALD + ks * 8], ALD);
            wmma::load_matrix_sync(af[1], &As[(wm + 16) * ALD + ks * 8], ALD);
#pragma unroll
            for (int nt = 0; nt < 4; nt++)
                wmma::load_matrix_sync(bf[nt],
                    &Bs[ks * 8 * BLD + wn + nt * 16], BLD);
#pragma unroll
            for (int mt = 0; mt < 2; mt++)
#pragma unroll
                for (int nt = 0; nt < 4; nt++)
                    wmma::mma_sync(acc[mt][nt], af[mt], bf[nt], acc[mt][nt]);
        }

        if (more) {
            float* An = Asm[(kt + 1) & 1];
            float* Bn = Bsm[(kt + 1) & 1];
            An[ar * ALD + ak + 0] = wmma::__float_to_tf32(a0.x);
            An[ar * ALD + ak + 1] = wmma::__float_to_tf32(a0.y);
            An[ar * ALD + ak + 2] = wmma::__float_to_tf32(a0.z);
            An[ar * ALD + ak + 3] = wmma::__float_to_tf32(a0.w);
            An[(ar + 64) * ALD + ak + 0] = wmma::__float_to_tf32(a1.x);
            An[(ar + 64) * ALD + ak + 1] = wmma::__float_to_tf32(a1.y);
            An[(ar + 64) * ALD + ak + 2] = wmma::__float_to_tf32(a1.z);
            An[(ar + 64) * ALD + ak + 3] = wmma::__float_to_tf32(a1.w);
            Bn[bk * BLD + bc + 0] = wmma::__float_to_tf32(b0.x);
            Bn[bk * BLD + bc + 1] = wmma::__float_to_tf32(b0.y);
            Bn[bk * BLD + bc + 2] = wmma::__float_to_tf32(b0.z);
            Bn[bk * BLD + bc + 3] = wmma::__float_to_tf32(b0.w);
            Bn[(bk + 8) * BLD + bc + 0] = wmma::__float_to_tf32(b1.x);
            Bn[(bk + 8) * BLD + bc + 1] = wmma::__float_to_tf32(b1.y);
            Bn[(bk + 8) * BLD + bc + 2] = wmma::__float_to_tf32(b1.z);
            Bn[(bk + 8) * BLD + bc + 3] = wmma::__float_to_tf32(b1.w);
        }
        __syncthreads();
    }

#pragma unroll
    for (int mt = 0; mt < 2; mt++)
#pragma unroll
        for (int nt = 0; nt < 4; nt++)
            wmma::store_matrix_sync(
                C + (size_t)(bm * 128 + wm + mt * 16) * N
                  + bn * 128 + wn + nt * 16,
                acc[mt][nt], N, wmma::mem_row_major);
}

// ---------------------------------------------------------------------------
// Bias add for the output projection: out[r][c] += bias[c]
// ---------------------------------------------------------------------------
__global__ __launch_bounds__(256) void bias_out_kernel(
    float* __restrict__ out, const float* __restrict__ bias)
{
    const int i = (blockIdx.x * 256 + threadIdx.x) * 4;
    float4 v = *(float4*)(out + i);
    const float4 b = *(const float4*)(bias + (i & (EMB - 1)));
    v.x += b.x; v.y += b.y; v.z += b.z; v.w += b.w;
    *(float4*)(out + i) = v;
}

// ---------------------------------------------------------------------------
// WMMA TF32 flash attention, fragment-resident O.
// Block = 128 queries of one (b,h), 256 threads = 8 warps, warp owns 16 rows.
// Warp-uniform running max -> softmax & O-correction are uniform fragment
// element ops (legal on opaque accumulators). Row sums via ones-column in V
// (5th n-fragment). smem: Q + K + V + P = 108.5 KB -> 2 CTAs/SM.
// ---------------------------------------------------------------------------
#define QLD 68
#define KLD 68
#define VLD 84
#define PLD 68
#define AT_Q  0
#define AT_K  (AT_Q + 128 * QLD)
#define AT_V  (AT_K + 64 * KLD)
#define AT_P  (AT_V + 64 * VLD)
#define ATTN_SMEM_FLOATS (AT_P + 128 * PLD)
#define ATTN_SMEM_BYTES  (ATTN_SMEM_FLOATS * 4)

__global__ __launch_bounds__(256) void attn_wmma_kernel(
    const float* __restrict__ b_qkv)
{
    extern __shared__ float sm[];
    float* Qs = sm + AT_Q;     // [128][QLD] tf32, pre-scaled
    float* Ks = sm + AT_K;     // [64][KLD]  tf32
    float* Vs = sm + AT_V;     // [64][VLD]  tf32; col 64 = 1.0 (ones column)
    float* Ps = sm + AT_P;     // [128][PLD] P (tf32) during tiles; O at end

    const int tid  = threadIdx.x;
    const int lane = tid & 31, warp = tid >> 5;
    const int qb = warp * 16;            // warp's query-row base
    const int rowIdx = lane >> 1, half = lane & 1;

    const int qt = blockIdx.x;           // 0..15
    const int bh = blockIdx.y;           // 0..63
    const int bb = bh >> 4, h = bh & (NH - 1);
    const size_t rowbase = (size_t)bb * SEQ;
    const int qcol = h * HS, kcol = EMB + h * HS, vcol = 2 * EMB + h * HS;

    // load Q tile (scaled 1/8, +bias, tf32)
    for (int i = tid * 4; i < 128 * HS; i += 256 * 4) {
        const int rr = i >> 6, d = i & 63;
        const float4 q4 = *(const float4*)(
            qkv_tmp + (rowbase + qt * 128 + rr) * N3 + qcol + d);
        const float4 bq = *(const float4*)(b_qkv + qcol + d);
        Qs[rr * QLD + d + 0] = wmma::__float_to_tf32((q4.x + bq.x) * 0.125f);
        Qs[rr * QLD + d + 1] = wmma::__float_to_tf32((q4.y + bq.y) * 0.125f);
        Qs[rr * QLD + d + 2] = wmma::__float_to_tf32((q4.z + bq.z) * 0.125f);
        Qs[rr * QLD + d + 3] = wmma::__float_to_tf32((q4.w + bq.w) * 0.125f);
    }
    // init V ones-column region (cols 64..79; only col 64 = 1). Written once;
    // per-tile fills touch cols 0..63 only.
    for (int i = tid; i < 64 * 16; i += 256) {
        const int rr = i >> 4, c = 64 + (i & 15);
        Vs[rr * VLD + c] = (c == 64) ? wmma::__float_to_tf32(1.0f) : 0.0f;
    }

    wmma::fragment<wmma::accumulator, 16, 16, 8, float> pv[5];
#pragma unroll
    for (int nt = 0; nt < 5; nt++) wmma::fill_fragment(pv[nt], 0.0f);
    float mW = -1e30f;

    for (int kt = 0; kt < SEQ / 64; kt++) {
        __syncthreads();   // Q/ones init (kt=0) or prev-tile K/V readers done
        // K/V tile (+bias, tf32)
        for (int i = tid * 4; i < 64 * HS; i += 256 * 4) {
            const int rr = i >> 6, d = i & 63;
            const size_t grow = rowbase + kt * 64 + rr;
            const float4 k4 = *(const float4*)(qkv_tmp + grow * N3 + kcol + d);
            const float4 bk = *(const float4*)(b_qkv + kcol + d);
            Ks[rr * KLD + d + 0] = wmma::__float_to_tf32(k4.x + bk.x);
            Ks[rr * KLD + d + 1] = wmma::__float_to_tf32(k4.y + bk.y);
            Ks[rr * KLD + d + 2] = wmma::__float_to_tf32(k4.z + bk.z);
            Ks[rr * KLD + d + 3] = wmma::__float_to_tf32(k4.w + bk.w);
            const float4 v4 = *(const float4*)(qkv_tmp + grow * N3 + vcol + d);
            const float4 bv = *(const float4*)(b_qkv + vcol + d);
            Vs[rr * VLD + d + 0] = wmma::__float_to_tf32(v4.x + bv.x);
            Vs[rr * VLD + d + 1] = wmma::__float_to_tf32(v4.y + bv.y);
            Vs[rr * VLD + d + 2] = wmma::__float_to_tf32(v4.z + bv.z);
            Vs[rr * VLD + d + 3] = wmma::__float_to_tf32(v4.w + bv.w);
        }
        __syncthreads();

        // ---- S = Q @ K^T  (warp: 16 x 64) ----
        wmma::fragment<wmma::accumulator, 16, 16, 8, float> sacc[4];
#pragma unroll
        for (int nt = 0; nt < 4; nt++) wmma::fill_fragment(sacc[nt], 0.0f);
#pragma unroll
        for (int d0 = 0; d0 < HS; d0 += 8) {
            wmma::fragment<wmma::matrix_a, 16, 16, 8,
                           wmma::precision::tf32, wmma::row_major> af;
            wmma::load_matrix_sync(af, &Qs[qb * QLD + d0], QLD);
#pragma unroll
            for (int nt = 0; nt < 4; nt++) {
                wmma::fragment<wmma::matrix_b, 16, 16, 8,
                               wmma::precision::tf32, wmma::col_major> bf;
                wmma::load_matrix_sync(bf, &Ks[(nt * 16) * KLD + d0], KLD);
                wmma::mma_sync(sacc[nt], af, bf, sacc[nt]);
            }
        }

        // ---- warp-uniform online max ----
        float mx = -1e30f;
#pragma unroll
        for (int nt = 0; nt < 4; nt++)
#pragma unroll
            for (int e = 0; e < sacc[nt].num_elements; e++)
                mx = fmaxf(mx, sacc[nt].x[e]);
#pragma unroll
        for (int off = 16; off > 0; off >>= 1)
            mx = fmaxf(mx, __shfl_xor_sync(0xffffffff, mx, off));
        const float mn = fmaxf(mW, mx);
        const float corr = __expf(mW - mn);
        mW = mn;

        // ---- O *= corr (uniform on fragment elements) ----
#pragma unroll
        for (int nt = 0; nt < 5; nt++)
#pragma unroll
            for (int e = 0; e < pv[nt].num_elements; e++)
                pv[nt].x[e] *= corr;

        // ---- P = exp(S - m), store as tf32 ----
#pragma unroll
        for (int nt = 0; nt < 4; nt++) {
#pragma unroll
            for (int e = 0; e < sacc[nt].num_elements; e++)
                sacc[nt].x[e] =
                    wmma::__float_to_tf32(__expf(sacc[nt].x[e] - mn));
            wmma::store_matrix_sync(&Ps[qb * PLD + nt * 16], sacc[nt],
                                    PLD, wmma::mem_row_major);
        }
        __syncwarp();

        // ---- O += P @ V'  (V' has ones-column at 64 -> pv[4] col0 = l) ----
#pragma unroll
        for (int kk = 0; kk < 64; kk += 8) {
            wmma::fragment<wmma::matrix_a, 16, 16, 8,
                           wmma::precision::tf32, wmma::row_major> af;
            wmma::load_matrix_sync(af, &Ps[qb * PLD + kk], PLD);
#pragma unroll
            for (int nt = 0; nt < 5; nt++) {
                wmma::fragment<wmma::matrix_b, 16, 16, 8,
                               wmma::precision::tf32, wmma::row_major> bf;
                wmma::load_matrix_sync(bf, &Vs[kk * VLD + nt * 16], VLD);
                wmma::mma_sync(pv[nt], af, bf, pv[nt]);
            }
        }
    }

    // ---- epilogue: extract l, normalize, write ----
    // 1) park pv[4] (cols 64..79; local col 0 = l) in P region, read l
    wmma::store_matrix_sync(&Ps[qb * PLD], pv[4], PLD, wmma::mem_row_major);
    __syncwarp();
    const float lval = Ps[(qb + rowIdx) * PLD + 0];
    __syncwarp();
    // 2) store O, normalize per lane (2 lanes per row)
#pragma unroll
    for (int nt = 0; nt < 4; nt++)
        wmma::store_matrix_sync(&Ps[qb * PLD + nt * 16], pv[nt],
                                PLD, wmma::mem_row_major);
    __syncwarp();

    const float inv = 1.0f / lval;
    const int r = qb + rowIdx;
    float* orow = g_att + (size_t)(rowbase + qt * 128 + r) * EMB
                  + h * HS + half * 32;
    const float* prow = &Ps[r * PLD + half * 32];
#pragma unroll
    for (int j = 0; j < 32; j += 4) {
        const float4 o4 = *(const float4*)&prow[j];
        *(float4*)&orow[j] = make_float4(o4.x * inv, o4.y * inv,
                                         o4.z * inv, o4.w * inv);
    }
}

// ---------------------------------------------------------------------------
extern "C" void kernel_launch(void* const* d_in, const int* in_sizes, int n_in,
                              void* d_out, int out_size)
{
    const float* x     = (const float*)d_in[0];
    const float* w_qkv = (const float*)d_in[1];
    const float* b_qkv = (const float*)d_in[2];
    const float* w_out = (const float*)d_in[3];
    const float* b_out = (const float*)d_in[4];
    float* out = (float*)d_out;

    float* qkv_ptr = nullptr;
    float* att_ptr = nullptr;
    cudaGetSymbolAddress((void**)&qkv_ptr, qkv_tmp);
    cudaGetSymbolAddress((void**)&att_ptr, g_att);

    // QKV projection (raw, bias folded into attention load)
    wmma_gemm_kernel<<<dim3(N3 / 128, MROWS / 128), 256>>>(
        x, w_qkv, qkv_ptr, N3);

    cudaFuncSetAttribute(attn_wmma_kernel,
                         cudaFuncAttributeMaxDynamicSharedMemorySize,
                         ATTN_SMEM_BYTES);
    attn_wmma_kernel<<<dim3(SEQ / 128, BATCH * NH), 256, ATTN_SMEM_BYTES>>>(
        b_qkv);

    // Output projection (raw) + bias
    wmma_gemm_kernel<<<dim3(EMB / 128, MROWS / 128), 256>>>(
        att_ptr, w_out, out, EMB);
    bias_out_kernel<<<(MROWS * EMB) / (256 * 4), 256>>>(out, b_out);
}

// round 11
// speedup vs baseline: 1.5650x; 1.2287x over previous
#include <cuda_runtime.h>
#include <mma.h>

using namespace nvcuda;

#define EMB   1024
#define NH    16
#define HS    64
#define BATCH 4
#define SEQ   2048
#define MROWS (BATCH * SEQ)   // 8192
#define N3    (3 * EMB)       // 3072

// Scratch (allocation-free rule: __device__ globals)
__device__ float qkv_tmp[MROWS * N3];    // [B*T][3C], raw (no bias)
__device__ float g_att[MROWS * EMB];     // [B][T][C] head-concat

// ---------------------------------------------------------------------------
// WMMA TF32 GEMM: C[8192, N] = A[8192, 1024] @ W[1024, N]   (no bias)
// block 128x128, BK=16, 256 threads = 8 warps, warp tile 32x64 (2x4 frags)
// Double-buffered smem, register-staged prefetch, ONE sync per k-tile.
// (unchanged from the passing Round-10 kernel)
// ---------------------------------------------------------------------------
#define ALD 20
#define BLD 136

__global__ __launch_bounds__(256) void wmma_gemm_kernel(
    const float* __restrict__ A, const float* __restrict__ W,
    float* __restrict__ C, int N)
{
    __shared__ float Asm[2][128 * ALD];
    __shared__ float Bsm[2][16 * BLD];

    const int tid  = threadIdx.x;
    const int warp = tid >> 5;
    const int bm = blockIdx.y, bn = blockIdx.x;
    const int wm = (warp & 3) * 32;
    const int wn = (warp >> 2) * 64;

    const int ar = tid >> 2, ak = (tid & 3) * 4;
    const int bk = tid >> 5, bc = (tid & 31) * 4;

    const float* ApG0 = A + (size_t)(bm * 128 + ar) * EMB + ak;
    const float* ApG1 = A + (size_t)(bm * 128 + ar + 64) * EMB + ak;
    const float* BpG0 = W + (size_t)bk * N + bn * 128 + bc;
    const float* BpG1 = W + (size_t)(bk + 8) * N + bn * 128 + bc;

    wmma::fragment<wmma::accumulator, 16, 16, 8, float> acc[2][4];
#pragma unroll
    for (int mt = 0; mt < 2; mt++)
#pragma unroll
        for (int nt = 0; nt < 4; nt++)
            wmma::fill_fragment(acc[mt][nt], 0.0f);

    // prologue: tile 0 -> buf 0
    {
        const float4 a0 = *(const float4*)(ApG0);
        const float4 a1 = *(const float4*)(ApG1);
        const float4 b0 = *(const float4*)(BpG0);
        const float4 b1 = *(const float4*)(BpG1);
        float* As = Asm[0];
        float* Bs = Bsm[0];
        As[ar * ALD + ak + 0] = wmma::__float_to_tf32(a0.x);
        As[ar * ALD + ak + 1] = wmma::__float_to_tf32(a0.y);
        As[ar * ALD + ak + 2] = wmma::__float_to_tf32(a0.z);
        As[ar * ALD + ak + 3] = wmma::__float_to_tf32(a0.w);
        As[(ar + 64) * ALD + ak + 0] = wmma::__float_to_tf32(a1.x);
        As[(ar + 64) * ALD + ak + 1] = wmma::__float_to_tf32(a1.y);
        As[(ar + 64) * ALD + ak + 2] = wmma::__float_to_tf32(a1.z);
        As[(ar + 64) * ALD + ak + 3] = wmma::__float_to_tf32(a1.w);
        Bs[bk * BLD + bc + 0] = wmma::__float_to_tf32(b0.x);
        Bs[bk * BLD + bc + 1] = wmma::__float_to_tf32(b0.y);
        Bs[bk * BLD + bc + 2] = wmma::__float_to_tf32(b0.z);
        Bs[bk * BLD + bc + 3] = wmma::__float_to_tf32(b0.w);
        Bs[(bk + 8) * BLD + bc + 0] = wmma::__float_to_tf32(b1.x);
        Bs[(bk + 8) * BLD + bc + 1] = wmma::__float_to_tf32(b1.y);
        Bs[(bk + 8) * BLD + bc + 2] = wmma::__float_to_tf32(b1.z);
        Bs[(bk + 8) * BLD + bc + 3] = wmma::__float_to_tf32(b1.w);
    }
    __syncthreads();

    const int NK = EMB / 16;   // 64
    for (int kt = 0; kt < NK; kt++) {
        float4 a0, a1, b0, b1;
        const bool more = (kt + 1 < NK);
        if (more) {
            const int ko = (kt + 1) * 16;
            a0 = *(const float4*)(ApG0 + ko);
            a1 = *(const float4*)(ApG1 + ko);
            b0 = *(const float4*)(BpG0 + (size_t)ko * N);
            b1 = *(const float4*)(BpG1 + (size_t)ko * N);
        }

        const float* As = Asm[kt & 1];
        const float* Bs = Bsm[kt & 1];
#pragma unroll
        for (int ks = 0; ks < 2; ks++) {
            wmma::fragment<wmma::matrix_a, 16, 16, 8,
                           wmma::precision::tf32, wmma::row_major> af[2];
            wmma::fragment<wmma::matrix_b, 16, 16, 8,
                           wmma::precision::tf32, wmma::row_major> bf[4];
            wmma::load_matrix_sync(af[0], &As[wm * ALD + ks * 8], ALD);
            wmma::load_matrix_sync(af[1], &As[(wm + 16) * ALD + ks * 8], ALD);
#pragma unroll
            for (int nt = 0; nt < 4; nt++)
                wmma::load_matrix_sync(bf[nt],
                    &Bs[ks * 8 * BLD + wn + nt * 16], BLD);
#pragma unroll
            for (int mt = 0; mt < 2; mt++)
#pragma unroll
                for (int nt = 0; nt < 4; nt++)
                    wmma::mma_sync(acc[mt][nt], af[mt], bf[nt], acc[mt][nt]);
        }

        if (more) {
            float* An = Asm[(kt + 1) & 1];
            float* Bn = Bsm[(kt + 1) & 1];
            An[ar * ALD + ak + 0] = wmma::__float_to_tf32(a0.x);
            An[ar * ALD + ak + 1] = wmma::__float_to_tf32(a0.y);
            An[ar * ALD + ak + 2] = wmma::__float_to_tf32(a0.z);
            An[ar * ALD + ak + 3] = wmma::__float_to_tf32(a0.w);
            An[(ar + 64) * ALD + ak + 0] = wmma::__float_to_tf32(a1.x);
            An[(ar + 64) * ALD + ak + 1] = wmma::__float_to_tf32(a1.y);
            An[(ar + 64) * ALD + ak + 2] = wmma::__float_to_tf32(a1.z);
            An[(ar + 64) * ALD + ak + 3] = wmma::__float_to_tf32(a1.w);
            Bn[bk * BLD + bc + 0] = wmma::__float_to_tf32(b0.x);
            Bn[bk * BLD + bc + 1] = wmma::__float_to_tf32(b0.y);
            Bn[bk * BLD + bc + 2] = wmma::__float_to_tf32(b0.z);
            Bn[bk * BLD + bc + 3] = wmma::__float_to_tf32(b0.w);
            Bn[(bk + 8) * BLD + bc + 0] = wmma::__float_to_tf32(b1.x);
            Bn[(bk + 8) * BLD + bc + 1] = wmma::__float_to_tf32(b1.y);
            Bn[(bk + 8) * BLD + bc + 2] = wmma::__float_to_tf32(b1.z);
            Bn[(bk + 8) * BLD + bc + 3] = wmma::__float_to_tf32(b1.w);
        }
        __syncthreads();
    }

#pragma unroll
    for (int mt = 0; mt < 2; mt++)
#pragma unroll
        for (int nt = 0; nt < 4; nt++)
            wmma::store_matrix_sync(
                C + (size_t)(bm * 128 + wm + mt * 16) * N
                  + bn * 128 + wn + nt * 16,
                acc[mt][nt], N, wmma::mem_row_major);
}

// ---------------------------------------------------------------------------
// Bias add for the output projection: out[r][c] += bias[c]
// ---------------------------------------------------------------------------
__global__ __launch_bounds__(256) void bias_out_kernel(
    float* __restrict__ out, const float* __restrict__ bias)
{
    const int i = (blockIdx.x * 256 + threadIdx.x) * 4;
    float4 v = *(float4*)(out + i);
    const float4 b = *(const float4*)(bias + (i & (EMB - 1)));
    v.x += b.x; v.y += b.y; v.z += b.z; v.w += b.w;
    *(float4*)(out + i) = v;
}

// ---------------------------------------------------------------------------
// WMMA TF32 flash attention, fragment-resident O.
// Block = 128 queries of one (b,h), 128 threads = 4 warps, warp owns 32 rows.
// B-fragments (K, V) reused across 2 m-tiles in registers: LDS-instr/mma
// drops from 5.0 / 4.8 to 3.0 / 2.8 in the S and PV loops.
// Warp-uniform running max; row sums via ones-column in V (5th n-fragment).
// smem 108.5 KB -> 2 CTAs/SM (8 warps/SM).
// ---------------------------------------------------------------------------
#define QLD 68
#define KLD 68
#define VLD 84
#define PLD 68
#define AT_Q  0
#define AT_K  (AT_Q + 128 * QLD)
#define AT_V  (AT_K + 64 * KLD)
#define AT_P  (AT_V + 64 * VLD)
#define ATTN_SMEM_FLOATS (AT_P + 128 * PLD)
#define ATTN_SMEM_BYTES  (ATTN_SMEM_FLOATS * 4)

__global__ __launch_bounds__(128) void attn_wmma_kernel(
    const float* __restrict__ b_qkv)
{
    extern __shared__ float sm[];
    float* Qs = sm + AT_Q;     // [128][QLD] tf32, pre-scaled
    float* Ks = sm + AT_K;     // [64][KLD]  tf32
    float* Vs = sm + AT_V;     // [64][VLD]  tf32; col 64 = 1.0 (ones column)
    float* Ps = sm + AT_P;     // [128][PLD] P (tf32) during tiles; O at end

    const int tid  = threadIdx.x;
    const int lane = tid & 31, warp = tid >> 5;
    const int qb = warp * 32;            // warp's 32-row base
    const int rowIdx = lane >> 1, half = lane & 1;

    const int qt = blockIdx.x;           // 0..15
    const int bh = blockIdx.y;           // 0..63
    const int bb = bh >> 4, h = bh & (NH - 1);
    const size_t rowbase = (size_t)bb * SEQ;
    const int qcol = h * HS, kcol = EMB + h * HS, vcol = 2 * EMB + h * HS;

    // load Q tile (scaled 1/8, +bias, tf32)
    for (int i = tid * 4; i < 128 * HS; i += 128 * 4) {
        const int rr = i >> 6, d = i & 63;
        const float4 q4 = *(const float4*)(
            qkv_tmp + (rowbase + qt * 128 + rr) * N3 + qcol + d);
        const float4 bq = *(const float4*)(b_qkv + qcol + d);
        Qs[rr * QLD + d + 0] = wmma::__float_to_tf32((q4.x + bq.x) * 0.125f);
        Qs[rr * QLD + d + 1] = wmma::__float_to_tf32((q4.y + bq.y) * 0.125f);
        Qs[rr * QLD + d + 2] = wmma::__float_to_tf32((q4.z + bq.z) * 0.125f);
        Qs[rr * QLD + d + 3] = wmma::__float_to_tf32((q4.w + bq.w) * 0.125f);
    }
    // init V ones-column region (cols 64..79; only col 64 = 1). Written once.
    for (int i = tid; i < 64 * 16; i += 128) {
        const int rr = i >> 4, c = 64 + (i & 15);
        Vs[rr * VLD + c] = (c == 64) ? wmma::__float_to_tf32(1.0f) : 0.0f;
    }

    wmma::fragment<wmma::accumulator, 16, 16, 8, float> pv[2][5];
#pragma unroll
    for (int mt = 0; mt < 2; mt++)
#pragma unroll
        for (int nt = 0; nt < 5; nt++)
            wmma::fill_fragment(pv[mt][nt], 0.0f);
    float mW = -1e30f;

    for (int kt = 0; kt < SEQ / 64; kt++) {
        __syncthreads();   // Q/ones init (kt=0) or prev-tile K/V readers done
        // K/V tile (+bias, tf32)
        for (int i = tid * 4; i < 64 * HS; i += 128 * 4) {
            const int rr = i >> 6, d = i & 63;
            const size_t grow = rowbase + kt * 64 + rr;
            const float4 k4 = *(const float4*)(qkv_tmp + grow * N3 + kcol + d);
            const float4 bk = *(const float4*)(b_qkv + kcol + d);
            Ks[rr * KLD + d + 0] = wmma::__float_to_tf32(k4.x + bk.x);
            Ks[rr * KLD + d + 1] = wmma::__float_to_tf32(k4.y + bk.y);
            Ks[rr * KLD + d + 2] = wmma::__float_to_tf32(k4.z + bk.z);
            Ks[rr * KLD + d + 3] = wmma::__float_to_tf32(k4.w + bk.w);
            const float4 v4 = *(const float4*)(qkv_tmp + grow * N3 + vcol + d);
            const float4 bv = *(const float4*)(b_qkv + vcol + d);
            Vs[rr * VLD + d + 0] = wmma::__float_to_tf32(v4.x + bv.x);
            Vs[rr * VLD + d + 1] = wmma::__float_to_tf32(v4.y + bv.y);
            Vs[rr * VLD + d + 2] = wmma::__float_to_tf32(v4.z + bv.z);
            Vs[rr * VLD + d + 3] = wmma::__float_to_tf32(v4.w + bv.w);
        }
        __syncthreads();

        // ---- S = Q @ K^T  (warp: 32 x 64) ----
        wmma::fragment<wmma::accumulator, 16, 16, 8, float> sacc[2][4];
#pragma unroll
        for (int mt = 0; mt < 2; mt++)
#pragma unroll
            for (int nt = 0; nt < 4; nt++)
                wmma::fill_fragment(sacc[mt][nt], 0.0f);
#pragma unroll
        for (int d0 = 0; d0 < HS; d0 += 8) {
            wmma::fragment<wmma::matrix_a, 16, 16, 8,
                           wmma::precision::tf32, wmma::row_major> af[2];
            wmma::load_matrix_sync(af[0], &Qs[qb * QLD + d0], QLD);
            wmma::load_matrix_sync(af[1], &Qs[(qb + 16) * QLD + d0], QLD);
#pragma unroll
            for (int nt = 0; nt < 4; nt++) {
                wmma::fragment<wmma::matrix_b, 16, 16, 8,
                               wmma::precision::tf32, wmma::col_major> bf;
                wmma::load_matrix_sync(bf, &Ks[(nt * 16) * KLD + d0], KLD);
#pragma unroll
                for (int mt = 0; mt < 2; mt++)
                    wmma::mma_sync(sacc[mt][nt], af[mt], bf, sacc[mt][nt]);
            }
        }

        // ---- warp-uniform online max over the warp's 32 rows ----
        float mx = -1e30f;
#pragma unroll
        for (int mt = 0; mt < 2; mt++)
#pragma unroll
            for (int nt = 0; nt < 4; nt++)
#pragma unroll
                for (int e = 0; e < sacc[mt][nt].num_elements; e++)
                    mx = fmaxf(mx, sacc[mt][nt].x[e]);
#pragma unroll
        for (int off = 16; off > 0; off >>= 1)
            mx = fmaxf(mx, __shfl_xor_sync(0xffffffff, mx, off));
        const float mn = fmaxf(mW, mx);
        const float corr = __expf(mW - mn);
        mW = mn;

        // ---- O *= corr (uniform on fragment elements) ----
#pragma unroll
        for (int mt = 0; mt < 2; mt++)
#pragma unroll
            for (int nt = 0; nt < 5; nt++)
#pragma unroll
                for (int e = 0; e < pv[mt][nt].num_elements; e++)
                    pv[mt][nt].x[e] *= corr;

        // ---- P = exp(S - m), store as tf32 ----
#pragma unroll
        for (int mt = 0; mt < 2; mt++)
#pragma unroll
            for (int nt = 0; nt < 4; nt++) {
#pragma unroll
                for (int e = 0; e < sacc[mt][nt].num_elements; e++)
                    sacc[mt][nt].x[e] =
                        wmma::__float_to_tf32(__expf(sacc[mt][nt].x[e] - mn));
                wmma::store_matrix_sync(&Ps[(qb + mt * 16) * PLD + nt * 16],
                                        sacc[mt][nt], PLD,
                                        wmma::mem_row_major);
            }
        __syncwarp();

        // ---- O += P @ V'  (ones-column at 64 -> pv[mt][4] col0 = l) ----
#pragma unroll
        for (int kk = 0; kk < 64; kk += 8) {
            wmma::fragment<wmma::matrix_a, 16, 16, 8,
                           wmma::precision::tf32, wmma::row_major> af[2];
            wmma::load_matrix_sync(af[0], &Ps[qb * PLD + kk], PLD);
            wmma::load_matrix_sync(af[1], &Ps[(qb + 16) * PLD + kk], PLD);
#pragma unroll
            for (int nt = 0; nt < 5; nt++) {
                wmma::fragment<wmma::matrix_b, 16, 16, 8,
                               wmma::precision::tf32, wmma::row_major> bf;
                wmma::load_matrix_sync(bf, &Vs[kk * VLD + nt * 16], VLD);
#pragma unroll
                for (int mt = 0; mt < 2; mt++)
                    wmma::mma_sync(pv[mt][nt], af[mt], bf, pv[mt][nt]);
            }
        }
    }

    // ---- epilogue: extract l, normalize, write ----
    // 1) park pv[mt][4] (local col 0 = l) in P region, read l per lane
    wmma::store_matrix_sync(&Ps[qb * PLD], pv[0][4], PLD,
                            wmma::mem_row_major);
    wmma::store_matrix_sync(&Ps[(qb + 16) * PLD], pv[1][4], PLD,
                            wmma::mem_row_major);
    __syncwarp();
    const float l0 = Ps[(qb + rowIdx) * PLD + 0];
    const float l1 = Ps[(qb + 16 + rowIdx) * PLD + 0];
    __syncwarp();
    // 2) store O into P region
#pragma unroll
    for (int mt = 0; mt < 2; mt++)
#pragma unroll
        for (int nt = 0; nt < 4; nt++)
            wmma::store_matrix_sync(&Ps[(qb + mt * 16) * PLD + nt * 16],
                                    pv[mt][nt], PLD, wmma::mem_row_major);
    __syncwarp();

    // 3) normalize + write (2 lanes per row, per mt)
#pragma unroll
    for (int mt = 0; mt < 2; mt++) {
        const float inv = 1.0f / (mt ? l1 : l0);
        const int r = qb + mt * 16 + rowIdx;
        float* orow = g_att + (size_t)(rowbase + qt * 128 + r) * EMB
                      + h * HS + half * 32;
        const float* prow = &Ps[r * PLD + half * 32];
#pragma unroll
        for (int j = 0; j < 32; j += 4) {
            const float4 o4 = *(const float4*)&prow[j];
            *(float4*)&orow[j] = make_float4(o4.x * inv, o4.y * inv,
                                             o4.z * inv, o4.w * inv);
        }
    }
}

// ---------------------------------------------------------------------------
extern "C" void kernel_launch(void* const* d_in, const int* in_sizes, int n_in,
                              void* d_out, int out_size)
{
    const float* x     = (const float*)d_in[0];
    const float* w_qkv = (const float*)d_in[1];
    const float* b_qkv = (const float*)d_in[2];
    const float* w_out = (const float*)d_in[3];
    const float* b_out = (const float*)d_in[4];
    float* out = (float*)d_out;

    float* qkv_ptr = nullptr;
    float* att_ptr = nullptr;
    cudaGetSymbolAddress((void**)&qkv_ptr, qkv_tmp);
    cudaGetSymbolAddress((void**)&att_ptr, g_att);

    // QKV projection (raw, bias folded into attention load)
    wmma_gemm_kernel<<<dim3(N3 / 128, MROWS / 128), 256>>>(
        x, w_qkv, qkv_ptr, N3);

    cudaFuncSetAttribute(attn_wmma_kernel,
                         cudaFuncAttributeMaxDynamicSharedMemorySize,
                         ATTN_SMEM_BYTES);
    attn_wmma_kernel<<<dim3(SEQ / 128, BATCH * NH), 128, ATTN_SMEM_BYTES>>>(
        b_qkv);

    // Output projection (raw) + bias
    wmma_gemm_kernel<<<dim3(EMB / 128, MROWS / 128), 256>>>(
        att_ptr, w_out, out, EMB);
    bias_out_kernel<<<(MROWS * EMB) / (256 * 4), 256>>>(out, b_out);
}

// round 12
// speedup vs baseline: 3.1632x; 2.0212x over previous
#include <cuda_runtime.h>
#include <mma.h>
#include <cuda_fp16.h>

using namespace nvcuda;

#define EMB   1024
#define NH    16
#define HS    64
#define BATCH 4
#define SEQ   2048
#define MROWS (BATCH * SEQ)   // 8192
#define N3    (3 * EMB)       // 3072

// Scratch (allocation-free rule: __device__ globals)
__device__ float qkv_tmp[MROWS * N3];    // [B*T][3C], raw (no bias)
__device__ float g_att[MROWS * EMB];     // [B][T][C] head-concat

__device__ __forceinline__ void st_half4(__half* p, float4 v) {
    *(__half2*)(p)     = __floats2half2_rn(v.x, v.y);
    *(__half2*)(p + 2) = __floats2half2_rn(v.z, v.w);
}

// ---------------------------------------------------------------------------
// FP16 WMMA GEMM: C[8192, N] = A[8192, 1024] @ W[1024, N]   (no bias)
// block 128x128, BK=16, 256 threads = 8 warps, warp tile 32x64.
// fp16 operands (same 10-bit mantissa as tf32), fp32 accumulate.
// m16n16k16 -> 8 mma + 6 LDSM fragment loads per k-tile (was 16 mma + 12
// scalar-LDS loads on tf32). Double-buffered, register prefetch, 1 sync/tile.
// ---------------------------------------------------------------------------
#define ALDH 24     // halfs per A row (16 + 8 pad)
#define BLDH 136    // halfs per B k-row (128 + 8 pad)

__global__ __launch_bounds__(256) void wmma_gemm_kernel(
    const float* __restrict__ A, const float* __restrict__ W,
    float* __restrict__ C, int N)
{
    __shared__ __half Asm[2][128 * ALDH];
    __shared__ __half Bsm[2][16 * BLDH];

    const int tid  = threadIdx.x;
    const int warp = tid >> 5;
    const int bm = blockIdx.y, bn = blockIdx.x;
    const int wm = (warp & 3) * 32;
    const int wn = (warp >> 2) * 64;

    const int ar = tid >> 2, ak = (tid & 3) * 4;
    const int bk = tid >> 5, bc = (tid & 31) * 4;

    const float* ApG0 = A + (size_t)(bm * 128 + ar) * EMB + ak;
    const float* ApG1 = A + (size_t)(bm * 128 + ar + 64) * EMB + ak;
    const float* BpG0 = W + (size_t)bk * N + bn * 128 + bc;
    const float* BpG1 = W + (size_t)(bk + 8) * N + bn * 128 + bc;

    wmma::fragment<wmma::accumulator, 16, 16, 16, float> acc[2][4];
#pragma unroll
    for (int mt = 0; mt < 2; mt++)
#pragma unroll
        for (int nt = 0; nt < 4; nt++)
            wmma::fill_fragment(acc[mt][nt], 0.0f);

    // prologue: tile 0 -> buf 0
    {
        st_half4(&Asm[0][ar * ALDH + ak],        *(const float4*)(ApG0));
        st_half4(&Asm[0][(ar + 64) * ALDH + ak], *(const float4*)(ApG1));
        st_half4(&Bsm[0][bk * BLDH + bc],        *(const float4*)(BpG0));
        st_half4(&Bsm[0][(bk + 8) * BLDH + bc],  *(const float4*)(BpG1));
    }
    __syncthreads();

    const int NK = EMB / 16;   // 64
    for (int kt = 0; kt < NK; kt++) {
        float4 a0, a1, b0, b1;
        const bool more = (kt + 1 < NK);
        if (more) {
            const int ko = (kt + 1) * 16;
            a0 = *(const float4*)(ApG0 + ko);
            a1 = *(const float4*)(ApG1 + ko);
            b0 = *(const float4*)(BpG0 + (size_t)ko * N);
            b1 = *(const float4*)(BpG1 + (size_t)ko * N);
        }

        const __half* As = Asm[kt & 1];
        const __half* Bs = Bsm[kt & 1];
        {
            wmma::fragment<wmma::matrix_a, 16, 16, 16, __half,
                           wmma::row_major> af[2];
            wmma::fragment<wmma::matrix_b, 16, 16, 16, __half,
                           wmma::row_major> bf[4];
            wmma::load_matrix_sync(af[0], &As[wm * ALDH], ALDH);
            wmma::load_matrix_sync(af[1], &As[(wm + 16) * ALDH], ALDH);
#pragma unroll
            for (int nt = 0; nt < 4; nt++)
                wmma::load_matrix_sync(bf[nt], &Bs[wn + nt * 16], BLDH);
#pragma unroll
            for (int mt = 0; mt < 2; mt++)
#pragma unroll
                for (int nt = 0; nt < 4; nt++)
                    wmma::mma_sync(acc[mt][nt], af[mt], bf[nt], acc[mt][nt]);
        }

        if (more) {
            __half* An = Asm[(kt + 1) & 1];
            __half* Bn = Bsm[(kt + 1) & 1];
            st_half4(&An[ar * ALDH + ak], a0);
            st_half4(&An[(ar + 64) * ALDH + ak], a1);
            st_half4(&Bn[bk * BLDH + bc], b0);
            st_half4(&Bn[(bk + 8) * BLDH + bc], b1);
        }
        __syncthreads();
    }

#pragma unroll
    for (int mt = 0; mt < 2; mt++)
#pragma unroll
        for (int nt = 0; nt < 4; nt++)
            wmma::store_matrix_sync(
                C + (size_t)(bm * 128 + wm + mt * 16) * N
                  + bn * 128 + wn + nt * 16,
                acc[mt][nt], N, wmma::mem_row_major);
}

// ---------------------------------------------------------------------------
// Bias add for the output projection: out[r][c] += bias[c]
// ---------------------------------------------------------------------------
__global__ __launch_bounds__(256) void bias_out_kernel(
    float* __restrict__ out, const float* __restrict__ bias)
{
    const int i = (blockIdx.x * 256 + threadIdx.x) * 4;
    float4 v = *(float4*)(out + i);
    const float4 b = *(const float4*)(bias + (i & (EMB - 1)));
    v.x += b.x; v.y += b.y; v.z += b.z; v.w += b.w;
    *(float4*)(out + i) = v;
}

// ---------------------------------------------------------------------------
// Flash attention: fp16 S-loop (Q,K half tiles, m16n16k16), tf32 PV.
// Block = 128 queries of one (b,h), 128 threads = 4 warps, warp owns 32 rows.
// Warp-uniform running max; row sums via ones-column in V (5th n-fragment);
// fragment-resident O. S accumulates fp32; P stored as float (tf32 PV).
// ---------------------------------------------------------------------------
#define QLDH 72     // halfs (64 + 8)
#define KLDH 72     // halfs
#define VLD  84     // floats; col 64 = ones
#define PLD  68     // floats
// byte offsets in dynamic smem
#define AT_Q_B  0
#define AT_K_B  (AT_Q_B + 128 * QLDH * 2)          // 18432
#define AT_V_B  (AT_K_B + 64 * KLDH * 2)           // +9216
#define AT_P_B  (AT_V_B + 64 * VLD * 4)            // +21504
#define ATTN_SMEM_BYTES (AT_P_B + 128 * PLD * 4)   // +34816 = 83968

__global__ __launch_bounds__(128) void attn_wmma_kernel(
    const float* __restrict__ b_qkv)
{
    extern __shared__ char smraw[];
    __half* Qs = (__half*)(smraw + AT_Q_B);   // [128][QLDH] half, pre-scaled
    __half* Ks = (__half*)(smraw + AT_K_B);   // [64][KLDH]  half
    float*  Vs = (float*)(smraw + AT_V_B);    // [64][VLD]   tf32 + ones col
    float*  Ps = (float*)(smraw + AT_P_B);    // [128][PLD]  float P / O

    const int tid  = threadIdx.x;
    const int lane = tid & 31, warp = tid >> 5;
    const int qb = warp * 32;            // warp's 32-row base
    const int rowIdx = lane >> 1, half = lane & 1;

    const int qt = blockIdx.x;           // 0..15
    const int bh = blockIdx.y;           // 0..63
    const int bb = bh >> 4, h = bh & (NH - 1);
    const size_t rowbase = (size_t)bb * SEQ;
    const int qcol = h * HS, kcol = EMB + h * HS, vcol = 2 * EMB + h * HS;

    // load Q tile (scaled 1/8, +bias, fp16)
    for (int i = tid * 4; i < 128 * HS; i += 128 * 4) {
        const int rr = i >> 6, d = i & 63;
        const float4 q4 = *(const float4*)(
            qkv_tmp + (rowbase + qt * 128 + rr) * N3 + qcol + d);
        const float4 bq = *(const float4*)(b_qkv + qcol + d);
        st_half4(&Qs[rr * QLDH + d],
                 make_float4((q4.x + bq.x) * 0.125f, (q4.y + bq.y) * 0.125f,
                             (q4.z + bq.z) * 0.125f, (q4.w + bq.w) * 0.125f));
    }
    // init V ones-column region (cols 64..79; only col 64 = 1). Written once.
    for (int i = tid; i < 64 * 16; i += 128) {
        const int rr = i >> 4, c = 64 + (i & 15);
        Vs[rr * VLD + c] = (c == 64) ? wmma::__float_to_tf32(1.0f) : 0.0f;
    }

    wmma::fragment<wmma::accumulator, 16, 16, 8, float> pv[2][5];
#pragma unroll
    for (int mt = 0; mt < 2; mt++)
#pragma unroll
        for (int nt = 0; nt < 5; nt++)
            wmma::fill_fragment(pv[mt][nt], 0.0f);
    float mW = -1e30f;

    for (int kt = 0; kt < SEQ / 64; kt++) {
        __syncthreads();   // Q/ones init (kt=0) or prev-tile K/V readers done
        // K (fp16) and V (tf32) tiles, +bias
        for (int i = tid * 4; i < 64 * HS; i += 128 * 4) {
            const int rr = i >> 6, d = i & 63;
            const size_t grow = rowbase + kt * 64 + rr;
            const float4 k4 = *(const float4*)(qkv_tmp + grow * N3 + kcol + d);
            const float4 bk = *(const float4*)(b_qkv + kcol + d);
            st_half4(&Ks[rr * KLDH + d],
                     make_float4(k4.x + bk.x, k4.y + bk.y,
                                 k4.z + bk.z, k4.w + bk.w));
            const float4 v4 = *(const float4*)(qkv_tmp + grow * N3 + vcol + d);
            const float4 bv = *(const float4*)(b_qkv + vcol + d);
            Vs[rr * VLD + d + 0] = wmma::__float_to_tf32(v4.x + bv.x);
            Vs[rr * VLD + d + 1] = wmma::__float_to_tf32(v4.y + bv.y);
            Vs[rr * VLD + d + 2] = wmma::__float_to_tf32(v4.z + bv.z);
            Vs[rr * VLD + d + 3] = wmma::__float_to_tf32(v4.w + bv.w);
        }
        __syncthreads();

        // ---- S = Q @ K^T  (warp: 32 x 64, fp16 m16n16k16) ----
        wmma::fragment<wmma::accumulator, 16, 16, 16, float> sacc[2][4];
#pragma unroll
        for (int mt = 0; mt < 2; mt++)
#pragma unroll
            for (int nt = 0; nt < 4; nt++)
                wmma::fill_fragment(sacc[mt][nt], 0.0f);
#pragma unroll
        for (int d0 = 0; d0 < HS; d0 += 16) {
            wmma::fragment<wmma::matrix_a, 16, 16, 16, __half,
                           wmma::row_major> af[2];
            wmma::load_matrix_sync(af[0], &Qs[qb * QLDH + d0], QLDH);
            wmma::load_matrix_sync(af[1], &Qs[(qb + 16) * QLDH + d0], QLDH);
#pragma unroll
            for (int nt = 0; nt < 4; nt++) {
                wmma::fragment<wmma::matrix_b, 16, 16, 16, __half,
                               wmma::col_major> bf;
                wmma::load_matrix_sync(bf, &Ks[(nt * 16) * KLDH + d0], KLDH);
#pragma unroll
                for (int mt = 0; mt < 2; mt++)
                    wmma::mma_sync(sacc[mt][nt], af[mt], bf, sacc[mt][nt]);
            }
        }

        // ---- warp-uniform online max over the warp's 32 rows ----
        float mx = -1e30f;
#pragma unroll
        for (int mt = 0; mt < 2; mt++)
#pragma unroll
            for (int nt = 0; nt < 4; nt++)
#pragma unroll
                for (int e = 0; e < sacc[mt][nt].num_elements; e++)
                    mx = fmaxf(mx, sacc[mt][nt].x[e]);
#pragma unroll
        for (int off = 16; off > 0; off >>= 1)
            mx = fmaxf(mx, __shfl_xor_sync(0xffffffff, mx, off));
        const float mn = fmaxf(mW, mx);
        const float corr = __expf(mW - mn);
        mW = mn;

        // ---- O *= corr (uniform on fragment elements) ----
#pragma unroll
        for (int mt = 0; mt < 2; mt++)
#pragma unroll
            for (int nt = 0; nt < 5; nt++)
#pragma unroll
                for (int e = 0; e < pv[mt][nt].num_elements; e++)
                    pv[mt][nt].x[e] *= corr;

        // ---- P = exp(S - m) (tf32), store to float P tile ----
#pragma unroll
        for (int mt = 0; mt < 2; mt++)
#pragma unroll
            for (int nt = 0; nt < 4; nt++) {
#pragma unroll
                for (int e = 0; e < sacc[mt][nt].num_elements; e++)
                    sacc[mt][nt].x[e] =
                        wmma::__float_to_tf32(__expf(sacc[mt][nt].x[e] - mn));
                wmma::store_matrix_sync(&Ps[(qb + mt * 16) * PLD + nt * 16],
                                        sacc[mt][nt], PLD,
                                        wmma::mem_row_major);
            }
        __syncwarp();

        // ---- O += P @ V'  (tf32; ones-column at 64 -> pv[mt][4] col0 = l)
#pragma unroll
        for (int kk = 0; kk < 64; kk += 8) {
            wmma::fragment<wmma::matrix_a, 16, 16, 8,
                           wmma::precision::tf32, wmma::row_major> af[2];
            wmma::load_matrix_sync(af[0], &Ps[qb * PLD + kk], PLD);
            wmma::load_matrix_sync(af[1], &Ps[(qb + 16) * PLD + kk], PLD);
#pragma unroll
            for (int nt = 0; nt < 5; nt++) {
                wmma::fragment<wmma::matrix_b, 16, 16, 8,
                               wmma::precision::tf32, wmma::row_major> bf;
                wmma::load_matrix_sync(bf, &Vs[kk * VLD + nt * 16], VLD);
#pragma unroll
                for (int mt = 0; mt < 2; mt++)
                    wmma::mma_sync(pv[mt][nt], af[mt], bf, pv[mt][nt]);
            }
        }
    }

    // ---- epilogue: extract l, normalize, write ----
    wmma::store_matrix_sync(&Ps[qb * PLD], pv[0][4], PLD,
                            wmma::mem_row_major);
    wmma::store_matrix_sync(&Ps[(qb + 16) * PLD], pv[1][4], PLD,
                            wmma::mem_row_major);
    __syncwarp();
    const float l0 = Ps[(qb + rowIdx) * PLD + 0];
    const float l1 = Ps[(qb + 16 + rowIdx) * PLD + 0];
    __syncwarp();
#pragma unroll
    for (int mt = 0; mt < 2; mt++)
#pragma unroll
        for (int nt = 0; nt < 4; nt++)
            wmma::store_matrix_sync(&Ps[(qb + mt * 16) * PLD + nt * 16],
                                    pv[mt][nt], PLD, wmma::mem_row_major);
    __syncwarp();

#pragma unroll
    for (int mt = 0; mt < 2; mt++) {
        const float inv = 1.0f / (mt ? l1 : l0);
        const int r = qb + mt * 16 + rowIdx;
        float* orow = g_att + (size_t)(rowbase + qt * 128 + r) * EMB
                      + h * HS + half * 32;
        const float* prow = &Ps[r * PLD + half * 32];
#pragma unroll
        for (int j = 0; j < 32; j += 4) {
            const float4 o4 = *(const float4*)&prow[j];
            *(float4*)&orow[j] = make_float4(o4.x * inv, o4.y * inv,
                                             o4.z * inv, o4.w * inv);
        }
    }
}

// ---------------------------------------------------------------------------
extern "C" void kernel_launch(void* const* d_in, const int* in_sizes, int n_in,
                              void* d_out, int out_size)
{
    const float* x     = (const float*)d_in[0];
    const float* w_qkv = (const float*)d_in[1];
    const float* b_qkv = (const float*)d_in[2];
    const float* w_out = (const float*)d_in[3];
    const float* b_out = (const float*)d_in[4];
    float* out = (float*)d_out;

    float* qkv_ptr = nullptr;
    float* att_ptr = nullptr;
    cudaGetSymbolAddress((void**)&qkv_ptr, qkv_tmp);
    cudaGetSymbolAddress((void**)&att_ptr, g_att);

    // QKV projection (raw, bias folded into attention load)
    wmma_gemm_kernel<<<dim3(N3 / 128, MROWS / 128), 256>>>(
        x, w_qkv, qkv_ptr, N3);

    cudaFuncSetAttribute(attn_wmma_kernel,
                         cudaFuncAttributeMaxDynamicSharedMemorySize,
                         ATTN_SMEM_BYTES);
    attn_wmma_kernel<<<dim3(SEQ / 128, BATCH * NH), 128, ATTN_SMEM_BYTES>>>(
        b_qkv);

    // Output projection (raw) + bias
    wmma_gemm_kernel<<<dim3(EMB / 128, MROWS / 128), 256>>>(
        att_ptr, w_out, out, EMB);
    bias_out_kernel<<<(MROWS * EMB) / (256 * 4), 256>>>(out, b_out);
}

// round 13
// speedup vs baseline: 4.6429x; 1.4678x over previous
#include <cuda_runtime.h>
#include <mma.h>
#include <cuda_fp16.h>

using namespace nvcuda;

#define EMB   1024
#define NH    16
#define HS    64
#define BATCH 4
#define SEQ   2048
#define MROWS (BATCH * SEQ)   // 8192
#define N3    (3 * EMB)       // 3072

// Scratch (allocation-free rule: __device__ globals)
__device__ float qkv_tmp[MROWS * N3];    // [B*T][3C], raw (no bias)
__device__ float g_att[MROWS * EMB];     // [B][T][C] head-concat

__device__ __forceinline__ void st_half4(__half* p, float4 v) {
    *(__half2*)(p)     = __floats2half2_rn(v.x, v.y);
    *(__half2*)(p + 2) = __floats2half2_rn(v.z, v.w);
}

// ---------------------------------------------------------------------------
// FP16 WMMA GEMM: C[8192, N] = A[8192, 1024] @ W[1024, N]   (no bias)
// (unchanged from the passing Round-12 kernel)
// ---------------------------------------------------------------------------
#define ALDH 24     // halfs per A row (16 + 8 pad)
#define BLDH 136    // halfs per B k-row (128 + 8 pad)

__global__ __launch_bounds__(256) void wmma_gemm_kernel(
    const float* __restrict__ A, const float* __restrict__ W,
    float* __restrict__ C, int N)
{
    __shared__ __half Asm[2][128 * ALDH];
    __shared__ __half Bsm[2][16 * BLDH];

    const int tid  = threadIdx.x;
    const int warp = tid >> 5;
    const int bm = blockIdx.y, bn = blockIdx.x;
    const int wm = (warp & 3) * 32;
    const int wn = (warp >> 2) * 64;

    const int ar = tid >> 2, ak = (tid & 3) * 4;
    const int bk = tid >> 5, bc = (tid & 31) * 4;

    const float* ApG0 = A + (size_t)(bm * 128 + ar) * EMB + ak;
    const float* ApG1 = A + (size_t)(bm * 128 + ar + 64) * EMB + ak;
    const float* BpG0 = W + (size_t)bk * N + bn * 128 + bc;
    const float* BpG1 = W + (size_t)(bk + 8) * N + bn * 128 + bc;

    wmma::fragment<wmma::accumulator, 16, 16, 16, float> acc[2][4];
#pragma unroll
    for (int mt = 0; mt < 2; mt++)
#pragma unroll
        for (int nt = 0; nt < 4; nt++)
            wmma::fill_fragment(acc[mt][nt], 0.0f);

    // prologue: tile 0 -> buf 0
    {
        st_half4(&Asm[0][ar * ALDH + ak],        *(const float4*)(ApG0));
        st_half4(&Asm[0][(ar + 64) * ALDH + ak], *(const float4*)(ApG1));
        st_half4(&Bsm[0][bk * BLDH + bc],        *(const float4*)(BpG0));
        st_half4(&Bsm[0][(bk + 8) * BLDH + bc],  *(const float4*)(BpG1));
    }
    __syncthreads();

    const int NK = EMB / 16;   // 64
    for (int kt = 0; kt < NK; kt++) {
        float4 a0, a1, b0, b1;
        const bool more = (kt + 1 < NK);
        if (more) {
            const int ko = (kt + 1) * 16;
            a0 = *(const float4*)(ApG0 + ko);
            a1 = *(const float4*)(ApG1 + ko);
            b0 = *(const float4*)(BpG0 + (size_t)ko * N);
            b1 = *(const float4*)(BpG1 + (size_t)ko * N);
        }

        const __half* As = Asm[kt & 1];
        const __half* Bs = Bsm[kt & 1];
        {
            wmma::fragment<wmma::matrix_a, 16, 16, 16, __half,
                           wmma::row_major> af[2];
            wmma::fragment<wmma::matrix_b, 16, 16, 16, __half,
                           wmma::row_major> bf[4];
            wmma::load_matrix_sync(af[0], &As[wm * ALDH], ALDH);
            wmma::load_matrix_sync(af[1], &As[(wm + 16) * ALDH], ALDH);
#pragma unroll
            for (int nt = 0; nt < 4; nt++)
                wmma::load_matrix_sync(bf[nt], &Bs[wn + nt * 16], BLDH);
#pragma unroll
            for (int mt = 0; mt < 2; mt++)
#pragma unroll
                for (int nt = 0; nt < 4; nt++)
                    wmma::mma_sync(acc[mt][nt], af[mt], bf[nt], acc[mt][nt]);
        }

        if (more) {
            __half* An = Asm[(kt + 1) & 1];
            __half* Bn = Bsm[(kt + 1) & 1];
            st_half4(&An[ar * ALDH + ak], a0);
            st_half4(&An[(ar + 64) * ALDH + ak], a1);
            st_half4(&Bn[bk * BLDH + bc], b0);
            st_half4(&Bn[(bk + 8) * BLDH + bc], b1);
        }
        __syncthreads();
    }

#pragma unroll
    for (int mt = 0; mt < 2; mt++)
#pragma unroll
        for (int nt = 0; nt < 4; nt++)
            wmma::store_matrix_sync(
                C + (size_t)(bm * 128 + wm + mt * 16) * N
                  + bn * 128 + wn + nt * 16,
                acc[mt][nt], N, wmma::mem_row_major);
}

// ---------------------------------------------------------------------------
// Bias add for the output projection: out[r][c] += bias[c]
// ---------------------------------------------------------------------------
__global__ __launch_bounds__(256) void bias_out_kernel(
    float* __restrict__ out, const float* __restrict__ bias)
{
    const int i = (blockIdx.x * 256 + threadIdx.x) * 4;
    float4 v = *(float4*)(out + i);
    const float4 b = *(const float4*)(bias + (i & (EMB - 1)));
    v.x += b.x; v.y += b.y; v.z += b.z; v.w += b.w;
    *(float4*)(out + i) = v;
}

// ---------------------------------------------------------------------------
// Flash attention: fp16 S-loop AND fp16 PV-loop (m16n16k16 + LDSM).
// Block = 128 queries of one (b,h), 128 threads = 4 warps, warp owns 32 rows.
// S accumulates fp32; exp'd S stored to float P tile, warp-privately
// converted to a half P tile for the PV mma. V tile is half (ones col exact).
// Warp-uniform running max; row sums via ones-column (5th n-fragment);
// fragment-resident O.
// ---------------------------------------------------------------------------
#define QLDH 72     // halfs (64 + 8)
#define KLDH 72     // halfs
#define VLDH 88     // halfs (80 + 8); col 64 = ones
#define PLD  68     // floats (S / O staging)
#define PLDH 72     // halfs (P for mma)
// byte offsets in dynamic smem
#define AT_Q_B  0
#define AT_K_B  (AT_Q_B + 128 * QLDH * 2)          // 18432
#define AT_V_B  (AT_K_B + 64 * KLDH * 2)           // +9216
#define AT_P_B  (AT_V_B + 64 * VLDH * 2)           // +11264
#define AT_PH_B (AT_P_B + 128 * PLD * 4)           // +34816
#define ATTN_SMEM_BYTES (AT_PH_B + 128 * PLDH * 2) // +18432 = 92160

__global__ __launch_bounds__(128) void attn_wmma_kernel(
    const float* __restrict__ b_qkv)
{
    extern __shared__ char smraw[];
    __half* Qs = (__half*)(smraw + AT_Q_B);   // [128][QLDH] half, pre-scaled
    __half* Ks = (__half*)(smraw + AT_K_B);   // [64][KLDH]  half
    __half* Vs = (__half*)(smraw + AT_V_B);   // [64][VLDH]  half + ones col
    float*  Ps = (float*)(smraw + AT_P_B);    // [128][PLD]  float S / O
    __half* Ph = (__half*)(smraw + AT_PH_B);  // [128][PLDH] half P

    const int tid  = threadIdx.x;
    const int lane = tid & 31, warp = tid >> 5;
    const int qb = warp * 32;            // warp's 32-row base
    const int rowIdx = lane >> 1, half = lane & 1;

    const int qt = blockIdx.x;           // 0..15
    const int bh = blockIdx.y;           // 0..63
    const int bb = bh >> 4, h = bh & (NH - 1);
    const size_t rowbase = (size_t)bb * SEQ;
    const int qcol = h * HS, kcol = EMB + h * HS, vcol = 2 * EMB + h * HS;

    // load Q tile (scaled 1/8, +bias, fp16)
    for (int i = tid * 4; i < 128 * HS; i += 128 * 4) {
        const int rr = i >> 6, d = i & 63;
        const float4 q4 = *(const float4*)(
            qkv_tmp + (rowbase + qt * 128 + rr) * N3 + qcol + d);
        const float4 bq = *(const float4*)(b_qkv + qcol + d);
        st_half4(&Qs[rr * QLDH + d],
                 make_float4((q4.x + bq.x) * 0.125f, (q4.y + bq.y) * 0.125f,
                             (q4.z + bq.z) * 0.125f, (q4.w + bq.w) * 0.125f));
    }
    // init V ones-column region (cols 64..79; only col 64 = 1). Written once.
    for (int i = tid; i < 64 * 16; i += 128) {
        const int rr = i >> 4, c = 64 + (i & 15);
        Vs[rr * VLDH + c] = (c == 64) ? __float2half(1.0f) : __float2half(0.0f);
    }

    wmma::fragment<wmma::accumulator, 16, 16, 16, float> pv[2][5];
#pragma unroll
    for (int mt = 0; mt < 2; mt++)
#pragma unroll
        for (int nt = 0; nt < 5; nt++)
            wmma::fill_fragment(pv[mt][nt], 0.0f);
    float mW = -1e30f;

    for (int kt = 0; kt < SEQ / 64; kt++) {
        __syncthreads();   // Q/ones init (kt=0) or prev-tile K/V readers done
        // K, V tiles (+bias, fp16)
        for (int i = tid * 4; i < 64 * HS; i += 128 * 4) {
            const int rr = i >> 6, d = i & 63;
            const size_t grow = rowbase + kt * 64 + rr;
            const float4 k4 = *(const float4*)(qkv_tmp + grow * N3 + kcol + d);
            const float4 bk = *(const float4*)(b_qkv + kcol + d);
            st_half4(&Ks[rr * KLDH + d],
                     make_float4(k4.x + bk.x, k4.y + bk.y,
                                 k4.z + bk.z, k4.w + bk.w));
            const float4 v4 = *(const float4*)(qkv_tmp + grow * N3 + vcol + d);
            const float4 bv = *(const float4*)(b_qkv + vcol + d);
            st_half4(&Vs[rr * VLDH + d],
                     make_float4(v4.x + bv.x, v4.y + bv.y,
                                 v4.z + bv.z, v4.w + bv.w));
        }
        __syncthreads();

        // ---- S = Q @ K^T  (warp: 32 x 64, fp16 m16n16k16) ----
        wmma::fragment<wmma::accumulator, 16, 16, 16, float> sacc[2][4];
#pragma unroll
        for (int mt = 0; mt < 2; mt++)
#pragma unroll
            for (int nt = 0; nt < 4; nt++)
                wmma::fill_fragment(sacc[mt][nt], 0.0f);
#pragma unroll
        for (int d0 = 0; d0 < HS; d0 += 16) {
            wmma::fragment<wmma::matrix_a, 16, 16, 16, __half,
                           wmma::row_major> af[2];
            wmma::load_matrix_sync(af[0], &Qs[qb * QLDH + d0], QLDH);
            wmma::load_matrix_sync(af[1], &Qs[(qb + 16) * QLDH + d0], QLDH);
#pragma unroll
            for (int nt = 0; nt < 4; nt++) {
                wmma::fragment<wmma::matrix_b, 16, 16, 16, __half,
                               wmma::col_major> bf;
                wmma::load_matrix_sync(bf, &Ks[(nt * 16) * KLDH + d0], KLDH);
#pragma unroll
                for (int mt = 0; mt < 2; mt++)
                    wmma::mma_sync(sacc[mt][nt], af[mt], bf, sacc[mt][nt]);
            }
        }

        // ---- warp-uniform online max over the warp's 32 rows ----
        float mx = -1e30f;
#pragma unroll
        for (int mt = 0; mt < 2; mt++)
#pragma unroll
            for (int nt = 0; nt < 4; nt++)
#pragma unroll
                for (int e = 0; e < sacc[mt][nt].num_elements; e++)
                    mx = fmaxf(mx, sacc[mt][nt].x[e]);
#pragma unroll
        for (int off = 16; off > 0; off >>= 1)
            mx = fmaxf(mx, __shfl_xor_sync(0xffffffff, mx, off));
        const float mn = fmaxf(mW, mx);
        const float corr = __expf(mW - mn);
        mW = mn;

        // ---- O *= corr (uniform on fragment elements) ----
#pragma unroll
        for (int mt = 0; mt < 2; mt++)
#pragma unroll
            for (int nt = 0; nt < 5; nt++)
#pragma unroll
                for (int e = 0; e < pv[mt][nt].num_elements; e++)
                    pv[mt][nt].x[e] *= corr;

        // ---- P = exp(S - m) -> float tile -> half tile (warp-private) ----
#pragma unroll
        for (int mt = 0; mt < 2; mt++)
#pragma unroll
            for (int nt = 0; nt < 4; nt++) {
#pragma unroll
                for (int e = 0; e < sacc[mt][nt].num_elements; e++)
                    sacc[mt][nt].x[e] = __expf(sacc[mt][nt].x[e] - mn);
                wmma::store_matrix_sync(&Ps[(qb + mt * 16) * PLD + nt * 16],
                                        sacc[mt][nt], PLD,
                                        wmma::mem_row_major);
            }
        __syncwarp();
        // convert this warp's 32 rows x 64 cols to half
        for (int i = lane * 4; i < 32 * 64; i += 32 * 4) {
            const int rr = qb + (i >> 6), c = i & 63;
            st_half4(&Ph[rr * PLDH + c], *(const float4*)&Ps[rr * PLD + c]);
        }
        __syncwarp();

        // ---- O += P @ V'  (fp16 m16n16k16; ones col -> pv[mt][4] col0 = l)
#pragma unroll
        for (int kk = 0; kk < 64; kk += 16) {
            wmma::fragment<wmma::matrix_a, 16, 16, 16, __half,
                           wmma::row_major> af[2];
            wmma::load_matrix_sync(af[0], &Ph[qb * PLDH + kk], PLDH);
            wmma::load_matrix_sync(af[1], &Ph[(qb + 16) * PLDH + kk], PLDH);
#pragma unroll
            for (int nt = 0; nt < 5; nt++) {
                wmma::fragment<wmma::matrix_b, 16, 16, 16, __half,
                               wmma::row_major> bf;
                wmma::load_matrix_sync(bf, &Vs[kk * VLDH + nt * 16], VLDH);
#pragma unroll
                for (int mt = 0; mt < 2; mt++)
                    wmma::mma_sync(pv[mt][nt], af[mt], bf, pv[mt][nt]);
            }
        }
    }

    // ---- epilogue: extract l, normalize, write ----
    wmma::store_matrix_sync(&Ps[qb * PLD], pv[0][4], PLD,
                            wmma::mem_row_major);
    wmma::store_matrix_sync(&Ps[(qb + 16) * PLD], pv[1][4], PLD,
                            wmma::mem_row_major);
    __syncwarp();
    const float l0 = Ps[(qb + rowIdx) * PLD + 0];
    const float l1 = Ps[(qb + 16 + rowIdx) * PLD + 0];
    __syncwarp();
#pragma unroll
    for (int mt = 0; mt < 2; mt++)
#pragma unroll
        for (int nt = 0; nt < 4; nt++)
            wmma::store_matrix_sync(&Ps[(qb + mt * 16) * PLD + nt * 16],
                                    pv[mt][nt], PLD, wmma::mem_row_major);
    __syncwarp();

#pragma unroll
    for (int mt = 0; mt < 2; mt++) {
        const float inv = 1.0f / (mt ? l1 : l0);
        const int r = qb + mt * 16 + rowIdx;
        float* orow = g_att + (size_t)(rowbase + qt * 128 + r) * EMB
                      + h * HS + half * 32;
        const float* prow = &Ps[r * PLD + half * 32];
#pragma unroll
        for (int j = 0; j < 32; j += 4) {
            const float4 o4 = *(const float4*)&prow[j];
            *(float4*)&orow[j] = make_float4(o4.x * inv, o4.y * inv,
                                             o4.z * inv, o4.w * inv);
        }
    }
}

// ---------------------------------------------------------------------------
extern "C" void kernel_launch(void* const* d_in, const int* in_sizes, int n_in,
                              void* d_out, int out_size)
{
    const float* x     = (const float*)d_in[0];
    const float* w_qkv = (const float*)d_in[1];
    const float* b_qkv = (const float*)d_in[2];
    const float* w_out = (const float*)d_in[3];
    const float* b_out = (const float*)d_in[4];
    float* out = (float*)d_out;

    float* qkv_ptr = nullptr;
    float* att_ptr = nullptr;
    cudaGetSymbolAddress((void**)&qkv_ptr, qkv_tmp);
    cudaGetSymbolAddress((void**)&att_ptr, g_att);

    // QKV projection (raw, bias folded into attention load)
    wmma_gemm_kernel<<<dim3(N3 / 128, MROWS / 128), 256>>>(
        x, w_qkv, qkv_ptr, N3);

    cudaFuncSetAttribute(attn_wmma_kernel,
                         cudaFuncAttributeMaxDynamicSharedMemorySize,
                         ATTN_SMEM_BYTES);
    attn_wmma_kernel<<<dim3(SEQ / 128, BATCH * NH), 128, ATTN_SMEM_BYTES>>>(
        b_qkv);

    // Output projection (raw) + bias
    wmma_gemm_kernel<<<dim3(EMB / 128, MROWS / 128), 256>>>(
        att_ptr, w_out, out, EMB);
    bias_out_kernel<<<(MROWS * EMB) / (256 * 4), 256>>>(out, b_out);
}

// round 14
// speedup vs baseline: 4.8477x; 1.0441x over previous
#include <cuda_runtime.h>
#include <mma.h>
#include <cuda_fp16.h>
#include <cuda_pipeline.h>

using namespace nvcuda;

#define EMB   1024
#define NH    16
#define HS    64
#define BATCH 4
#define SEQ   2048
#define MROWS (BATCH * SEQ)   // 8192
#define N3    (3 * EMB)       // 3072

// Scratch (allocation-free rule: __device__ globals)
__device__ __half x_h[MROWS * EMB];
__device__ __half wqkv_h[EMB * N3];
__device__ __half wout_h[EMB * EMB];
__device__ __half qkv_h[MROWS * N3];     // q pre-scaled+biased; k,v biased
__device__ __half g_att_h[MROWS * EMB];  // [B][T][C] head-concat

__device__ __forceinline__ void st_half4(__half* p, float4 v) {
    *(__half2*)(p)     = __floats2half2_rn(v.x, v.y);
    *(__half2*)(p + 2) = __floats2half2_rn(v.z, v.w);
}

// ---------------------------------------------------------------------------
// float -> half conversion (grid-stride-free: exact sizes, n % 2048 == 0)
// ---------------------------------------------------------------------------
__global__ __launch_bounds__(256) void f2h_kernel(
    const float* __restrict__ src, __half* __restrict__ dst)
{
    const int i = (blockIdx.x * 256 + threadIdx.x) * 8;
    const float4 a = *(const float4*)(src + i);
    const float4 b = *(const float4*)(src + i + 4);
    st_half4(dst + i, a);
    st_half4(dst + i + 4, b);
}

// ---------------------------------------------------------------------------
// FP16 WMMA GEMM, cp.async 3-stage pipeline:
//   C[8192, N] = A_h[8192, 1024] @ W_h[1024, N] + bias  (optional q-scale)
// block 128x128, BK=16, 256 threads = 8 warps, warp tile 32x64.
// Epilogue: accumulators staged through smem, bias fused, writes half or
// float. half_out selected by Ch != nullptr.
// ---------------------------------------------------------------------------
#define ALDH 24                 // halfs per A row (16 + 8)
#define BLDH 136                // halfs per B k-row (128 + 8)
#define ABUFH (128 * ALDH)      // 3072 halfs
#define BBUFH (16 * BLDH)       // 2176 halfs
#define STAGEH (ABUFH + BBUFH)  // 5248 halfs = 10496 B
#define GEMM_SMEM_BYTES (8 * 16 * 68 * 4)   // 34816 B (staging > 3*STAGEH)

__device__ __forceinline__ void gemm_issue_tile(
    __half* smem_h, int s, int kt,
    const __half* __restrict__ A, const __half* __restrict__ W,
    int bm, int bn, int N, int tid)
{
    // A tile: 256 chunks of 8 halfs; thread t -> row t>>1, chunk t&1
    {
        const int row = tid >> 1, c = tid & 1;
        __pipeline_memcpy_async(
            &smem_h[s * STAGEH + row * ALDH + c * 8],
            A + (size_t)(bm * 128 + row) * EMB + kt * 16 + c * 8, 16);
    }
    // B tile: 256 chunks; thread t -> k-row t>>4, chunk t&15
    {
        const int row = tid >> 4, c = tid & 15;
        __pipeline_memcpy_async(
            &smem_h[s * STAGEH + ABUFH + row * BLDH + c * 8],
            W + (size_t)(kt * 16 + row) * N + bn * 128 + c * 8, 16);
    }
    __pipeline_commit();
}

__global__ __launch_bounds__(256) void gemm_h_kernel(
    const __half* __restrict__ A, const __half* __restrict__ W,
    const float* __restrict__ bias,
    __half* __restrict__ Ch, float* __restrict__ Cf,
    int N, int qscale_flag)
{
    extern __shared__ char smraw[];
    __half* smh = (__half*)smraw;

    const int tid  = threadIdx.x;
    const int lane = tid & 31, warp = tid >> 5;
    const int bm = blockIdx.y, bn = blockIdx.x;
    const int wm = (warp & 3) * 32;
    const int wn = (warp >> 2) * 64;

    wmma::fragment<wmma::accumulator, 16, 16, 16, float> acc[2][4];
#pragma unroll
    for (int mt = 0; mt < 2; mt++)
#pragma unroll
        for (int nt = 0; nt < 4; nt++)
            wmma::fill_fragment(acc[mt][nt], 0.0f);

    // prologue: tiles 0,1 -> stages 0,1
    gemm_issue_tile(smh, 0, 0, A, W, bm, bn, N, tid);
    gemm_issue_tile(smh, 1, 1, A, W, bm, bn, N, tid);

    const int NK = EMB / 16;   // 64
    for (int kt = 0; kt < NK; kt++) {
        if (kt + 1 < NK) __pipeline_wait_prior(1);
        else             __pipeline_wait_prior(0);
        __syncthreads();

        const __half* As = smh + (kt % 3) * STAGEH;
        const __half* Bs = As + ABUFH;
        {
            wmma::fragment<wmma::matrix_a, 16, 16, 16, __half,
                           wmma::row_major> af[2];
            wmma::fragment<wmma::matrix_b, 16, 16, 16, __half,
                           wmma::row_major> bf[4];
            wmma::load_matrix_sync(af[0], &As[wm * ALDH], ALDH);
            wmma::load_matrix_sync(af[1], &As[(wm + 16) * ALDH], ALDH);
#pragma unroll
            for (int nt = 0; nt < 4; nt++)
                wmma::load_matrix_sync(bf[nt], &Bs[wn + nt * 16], BLDH);
#pragma unroll
            for (int mt = 0; mt < 2; mt++)
#pragma unroll
                for (int nt = 0; nt < 4; nt++)
                    wmma::mma_sync(acc[mt][nt], af[mt], bf[nt], acc[mt][nt]);
        }

        if (kt + 2 < NK)
            gemm_issue_tile(smh, (kt + 2) % 3, kt + 2, A, W, bm, bn, N, tid);
    }

    // ---- epilogue: stage via smem, fuse bias (+q-scale), write ----
    __syncthreads();           // all warps done reading pipeline buffers
    float* stg = (float*)smraw + warp * (16 * 68);
    const int r  = lane >> 1;
    const int c0 = (lane & 1) * 32;
#pragma unroll
    for (int mt = 0; mt < 2; mt++) {
#pragma unroll
        for (int nt = 0; nt < 4; nt++)
            wmma::store_matrix_sync(&stg[nt * 16], acc[mt][nt], 68,
                                    wmma::mem_row_major);
        __syncwarp();
        const int grow = bm * 128 + wm + mt * 16 + r;
        const int gcol = bn * 128 + wn + c0;   // multiple of 32
        const float qs = (qscale_flag && gcol < EMB) ? 0.125f : 1.0f;
#pragma unroll
        for (int j = 0; j < 32; j += 4) {
            float4 v = *(const float4*)&stg[r * 68 + c0 + j];
            const float4 b = *(const float4*)&bias[gcol + j];
            v.x = (v.x + b.x) * qs;
            v.y = (v.y + b.y) * qs;
            v.z = (v.z + b.z) * qs;
            v.w = (v.w + b.w) * qs;
            if (Ch) st_half4(&Ch[(size_t)grow * N + gcol + j], v);
            else    *(float4*)&Cf[(size_t)grow * N + gcol + j] = v;
        }
        __syncwarp();
    }
}

// ---------------------------------------------------------------------------
// Flash attention (fp16 S and PV, m16n16k16 + LDSM), half in / half out.
// Block = 128 queries of one (b,h), 128 threads = 4 warps, warp owns 32 rows.
// Fills are pure 16B copies (bias + q-scale pre-folded in the QKV GEMM).
// Warp-uniform running max; row sums via ones-column (5th n-fragment);
// fragment-resident O; O written half to g_att_h.
// ---------------------------------------------------------------------------
#define QLDH 72     // halfs (64 + 8)
#define KLDH 72
#define VLDH 88     // halfs (80 + 8); col 64 = ones
#define PLD  68     // floats (S / O staging)
#define PLDH 72     // halfs (P for mma)
#define AT_Q_B  0
#define AT_K_B  (AT_Q_B + 128 * QLDH * 2)          // 18432
#define AT_V_B  (AT_K_B + 64 * KLDH * 2)           // +9216
#define AT_P_B  (AT_V_B + 64 * VLDH * 2)           // +11264
#define AT_PH_B (AT_P_B + 128 * PLD * 4)           // +34816
#define ATTN_SMEM_BYTES (AT_PH_B + 128 * PLDH * 2) // +18432 = 92160

__global__ __launch_bounds__(128) void attn_wmma_kernel()
{
    extern __shared__ char smraw[];
    __half* Qs = (__half*)(smraw + AT_Q_B);   // [128][QLDH]
    __half* Ks = (__half*)(smraw + AT_K_B);   // [64][KLDH]
    __half* Vs = (__half*)(smraw + AT_V_B);   // [64][VLDH] + ones col
    float*  Ps = (float*)(smraw + AT_P_B);    // [128][PLD] float S / O
    __half* Ph = (__half*)(smraw + AT_PH_B);  // [128][PLDH] half P

    const int tid  = threadIdx.x;
    const int lane = tid & 31, warp = tid >> 5;
    const int qb = warp * 32;
    const int rowIdx = lane >> 1, half = lane & 1;

    const int qt = blockIdx.x;           // 0..15
    const int bh = blockIdx.y;           // 0..63
    const int bb = bh >> 4, h = bh & (NH - 1);
    const size_t rowbase = (size_t)bb * SEQ;
    const int qcol = h * HS, kcol = EMB + h * HS, vcol = 2 * EMB + h * HS;

    // Q tile: pure copy (pre-scaled, pre-biased)
    for (int i = tid * 8; i < 128 * HS; i += 128 * 8) {
        const int rr = i >> 6, d = i & 63;
        *(uint4*)&Qs[rr * QLDH + d] = *(const uint4*)(
            qkv_h + (rowbase + qt * 128 + rr) * N3 + qcol + d);
    }
    // ones column region (cols 64..79; only 64 = 1), written once
    for (int i = tid; i < 64 * 16; i += 128) {
        const int rr = i >> 4, c = 64 + (i & 15);
        Vs[rr * VLDH + c] = (c == 64) ? __float2half(1.0f)
                                      : __float2half(0.0f);
    }

    wmma::fragment<wmma::accumulator, 16, 16, 16, float> pv[2][5];
#pragma unroll
    for (int mt = 0; mt < 2; mt++)
#pragma unroll
        for (int nt = 0; nt < 5; nt++)
            wmma::fill_fragment(pv[mt][nt], 0.0f);
    float mW = -1e30f;

    for (int kt = 0; kt < SEQ / 64; kt++) {
        __syncthreads();
        // K/V tiles: pure copies
        for (int i = tid * 8; i < 64 * HS; i += 128 * 8) {
            const int rr = i >> 6, d = i & 63;
            const size_t grow = rowbase + kt * 64 + rr;
            *(uint4*)&Ks[rr * KLDH + d] =
                *(const uint4*)(qkv_h + grow * N3 + kcol + d);
            *(uint4*)&Vs[rr * VLDH + d] =
                *(const uint4*)(qkv_h + grow * N3 + vcol + d);
        }
        __syncthreads();

        // ---- S = Q @ K^T ----
        wmma::fragment<wmma::accumulator, 16, 16, 16, float> sacc[2][4];
#pragma unroll
        for (int mt = 0; mt < 2; mt++)
#pragma unroll
            for (int nt = 0; nt < 4; nt++)
                wmma::fill_fragment(sacc[mt][nt], 0.0f);
#pragma unroll
        for (int d0 = 0; d0 < HS; d0 += 16) {
            wmma::fragment<wmma::matrix_a, 16, 16, 16, __half,
                           wmma::row_major> af[2];
            wmma::load_matrix_sync(af[0], &Qs[qb * QLDH + d0], QLDH);
            wmma::load_matrix_sync(af[1], &Qs[(qb + 16) * QLDH + d0], QLDH);
#pragma unroll
            for (int nt = 0; nt < 4; nt++) {
                wmma::fragment<wmma::matrix_b, 16, 16, 16, __half,
                               wmma::col_major> bf;
                wmma::load_matrix_sync(bf, &Ks[(nt * 16) * KLDH + d0], KLDH);
#pragma unroll
                for (int mt = 0; mt < 2; mt++)
                    wmma::mma_sync(sacc[mt][nt], af[mt], bf, sacc[mt][nt]);
            }
        }

        // ---- warp-uniform online max ----
        float mx = -1e30f;
#pragma unroll
        for (int mt = 0; mt < 2; mt++)
#pragma unroll
            for (int nt = 0; nt < 4; nt++)
#pragma unroll
                for (int e = 0; e < sacc[mt][nt].num_elements; e++)
                    mx = fmaxf(mx, sacc[mt][nt].x[e]);
#pragma unroll
        for (int off = 16; off > 0; off >>= 1)
            mx = fmaxf(mx, __shfl_xor_sync(0xffffffff, mx, off));
        const float mn = fmaxf(mW, mx);
        const float corr = __expf(mW - mn);
        mW = mn;

        // ---- O *= corr ----
#pragma unroll
        for (int mt = 0; mt < 2; mt++)
#pragma unroll
            for (int nt = 0; nt < 5; nt++)
#pragma unroll
                for (int e = 0; e < pv[mt][nt].num_elements; e++)
                    pv[mt][nt].x[e] *= corr;

        // ---- P = exp(S - m) -> float tile -> half tile ----
#pragma unroll
        for (int mt = 0; mt < 2; mt++)
#pragma unroll
            for (int nt = 0; nt < 4; nt++) {
#pragma unroll
                for (int e = 0; e < sacc[mt][nt].num_elements; e++)
                    sacc[mt][nt].x[e] = __expf(sacc[mt][nt].x[e] - mn);
                wmma::store_matrix_sync(&Ps[(qb + mt * 16) * PLD + nt * 16],
                                        sacc[mt][nt], PLD,
                                        wmma::mem_row_major);
            }
        __syncwarp();
        for (int i = lane * 4; i < 32 * 64; i += 32 * 4) {
            const int rr = qb + (i >> 6), c = i & 63;
            st_half4(&Ph[rr * PLDH + c], *(const float4*)&Ps[rr * PLD + c]);
        }
        __syncwarp();

        // ---- O += P @ V' (ones col -> pv[mt][4] col0 = l) ----
#pragma unroll
        for (int kk = 0; kk < 64; kk += 16) {
            wmma::fragment<wmma::matrix_a, 16, 16, 16, __half,
                           wmma::row_major> af[2];
            wmma::load_matrix_sync(af[0], &Ph[qb * PLDH + kk], PLDH);
            wmma::load_matrix_sync(af[1], &Ph[(qb + 16) * PLDH + kk], PLDH);
#pragma unroll
            for (int nt = 0; nt < 5; nt++) {
                wmma::fragment<wmma::matrix_b, 16, 16, 16, __half,
                               wmma::row_major> bf;
                wmma::load_matrix_sync(bf, &Vs[kk * VLDH + nt * 16], VLDH);
#pragma unroll
                for (int mt = 0; mt < 2; mt++)
                    wmma::mma_sync(pv[mt][nt], af[mt], bf, pv[mt][nt]);
            }
        }
    }

    // ---- epilogue: extract l, normalize, write half ----
    wmma::store_matrix_sync(&Ps[qb * PLD], pv[0][4], PLD,
                            wmma::mem_row_major);
    wmma::store_matrix_sync(&Ps[(qb + 16) * PLD], pv[1][4], PLD,
                            wmma::mem_row_major);
    __syncwarp();
    const float l0 = Ps[(qb + rowIdx) * PLD + 0];
    const float l1 = Ps[(qb + 16 + rowIdx) * PLD + 0];
    __syncwarp();
#pragma unroll
    for (int mt = 0; mt < 2; mt++)
#pragma unroll
        for (int nt = 0; nt < 4; nt++)
            wmma::store_matrix_sync(&Ps[(qb + mt * 16) * PLD + nt * 16],
                                    pv[mt][nt], PLD, wmma::mem_row_major);
    __syncwarp();

#pragma unroll
    for (int mt = 0; mt < 2; mt++) {
        const float inv = 1.0f / (mt ? l1 : l0);
        const int r = qb + mt * 16 + rowIdx;
        __half* orow = g_att_h + (size_t)(rowbase + qt * 128 + r) * EMB
                       + h * HS + half * 32;
        const float* prow = &Ps[r * PLD + half * 32];
#pragma unroll
        for (int j = 0; j < 32; j += 4) {
            const float4 o4 = *(const float4*)&prow[j];
            st_half4(&orow[j], make_float4(o4.x * inv, o4.y * inv,
                                           o4.z * inv, o4.w * inv));
        }
    }
}

// ---------------------------------------------------------------------------
extern "C" void kernel_launch(void* const* d_in, const int* in_sizes, int n_in,
                              void* d_out, int out_size)
{
    const float* x     = (const float*)d_in[0];
    const float* w_qkv = (const float*)d_in[1];
    const float* b_qkv = (const float*)d_in[2];
    const float* w_out = (const float*)d_in[3];
    const float* b_out = (const float*)d_in[4];
    float* out = (float*)d_out;

    __half *xh_p, *wq_p, *wo_p, *qkv_p, *att_p;
    cudaGetSymbolAddress((void**)&xh_p,  x_h);
    cudaGetSymbolAddress((void**)&wq_p,  wqkv_h);
    cudaGetSymbolAddress((void**)&wo_p,  wout_h);
    cudaGetSymbolAddress((void**)&qkv_p, qkv_h);
    cudaGetSymbolAddress((void**)&att_p, g_att_h);

    // convert inputs to half
    f2h_kernel<<<(MROWS * EMB) / 2048, 256>>>(x, xh_p);
    f2h_kernel<<<(EMB * N3) / 2048, 256>>>(w_qkv, wq_p);
    f2h_kernel<<<(EMB * EMB) / 2048, 256>>>(w_out, wo_p);

    // QKV projection: bias fused, q-cols pre-scaled by 1/8, half out
    gemm_h_kernel<<<dim3(N3 / 128, MROWS / 128), 256, GEMM_SMEM_BYTES>>>(
        xh_p, wq_p, b_qkv, qkv_p, nullptr, N3, 1);

    cudaFuncSetAttribute(attn_wmma_kernel,
                         cudaFuncAttributeMaxDynamicSharedMemorySize,
                         ATTN_SMEM_BYTES);
    attn_wmma_kernel<<<dim3(SEQ / 128, BATCH * NH), 128, ATTN_SMEM_BYTES>>>();

    // Output projection: bias fused, float out
    gemm_h_kernel<<<dim3(EMB / 128, MROWS / 128), 256, GEMM_SMEM_BYTES>>>(
        att_p, wo_p, b_out, nullptr, out, EMB, 0);
}

// round 15
// speedup vs baseline: 6.1689x; 1.2725x over previous
#include <cuda_runtime.h>
#include <mma.h>
#include <cuda_fp16.h>
#include <cuda_pipeline.h>

using namespace nvcuda;

#define EMB   1024
#define NH    16
#define HS    64
#define BATCH 4
#define SEQ   2048
#define MROWS (BATCH * SEQ)   // 8192
#define N3    (3 * EMB)       // 3072

// Scratch (allocation-free rule: __device__ globals)
__device__ __half x_h[MROWS * EMB];
__device__ __half wqkv_h[EMB * N3];
__device__ __half wout_h[EMB * EMB];
__device__ __half qkv_h[MROWS * N3];     // q pre-scaled+biased; k,v biased
__device__ __half g_att_h[MROWS * EMB];  // [B][T][C] head-concat

__device__ __forceinline__ void st_half4(__half* p, float4 v) {
    *(__half2*)(p)     = __floats2half2_rn(v.x, v.y);
    *(__half2*)(p + 2) = __floats2half2_rn(v.z, v.w);
}

// ---------------------------------------------------------------------------
// float -> half conversion
// ---------------------------------------------------------------------------
__global__ __launch_bounds__(256) void f2h_kernel(
    const float* __restrict__ src, __half* __restrict__ dst)
{
    const int i = (blockIdx.x * 256 + threadIdx.x) * 8;
    const float4 a = *(const float4*)(src + i);
    const float4 b = *(const float4*)(src + i + 4);
    st_half4(dst + i, a);
    st_half4(dst + i + 4, b);
}

// ---------------------------------------------------------------------------
// FP16 WMMA GEMM, cp.async 4-stage pipeline, hoisted addressing:
//   C[8192, N] = A_h[8192, 1024] @ W_h[1024, N] + bias  (optional q-scale)
// block 128x128, BK=16, 256 threads = 8 warps, warp tile 32x64.
// ---------------------------------------------------------------------------
#define ALDH 24                 // halfs per A row (16 + 8)
#define BLDH 136                // halfs per B k-row (128 + 8)
#define ABUFH (128 * ALDH)      // 3072 halfs
#define BBUFH (16 * BLDH)       // 2176 halfs
#define STAGEH (ABUFH + BBUFH)  // 5248 halfs = 10496 B
#define GEMM_SMEM_BYTES (4 * STAGEH * 2)   // 41984 B (> epilogue 34816)

__global__ __launch_bounds__(256) void gemm_h_kernel(
    const __half* __restrict__ A, const __half* __restrict__ W,
    const float* __restrict__ bias,
    __half* __restrict__ Ch, float* __restrict__ Cf,
    int N, int qscale_flag)
{
    extern __shared__ char smraw[];
    __half* smh = (__half*)smraw;

    const int tid  = threadIdx.x;
    const int lane = tid & 31, warp = tid >> 5;
    const int bm = blockIdx.y, bn = blockIdx.x;
    const int wm = (warp & 3) * 32;
    const int wn = (warp >> 2) * 64;

    // hoisted cp.async addressing (per-thread constants)
    const int arow = tid >> 1, ac = (tid & 1) * 8;
    const int brow = tid >> 4, bc8 = (tid & 15) * 8;
    const __half* aSrc = A + (size_t)(bm * 128 + arow) * EMB + ac;
    const __half* bSrc = W + (size_t)brow * N + bn * 128 + bc8;
    const int aOff = arow * ALDH + ac;
    const int bOff = ABUFH + brow * BLDH + bc8;

#define GEMM_ISSUE(stage, kt)                                               \
    do {                                                                    \
        __pipeline_memcpy_async(&smh[(stage) * STAGEH + aOff],              \
                                aSrc + (kt) * 16, 16);                      \
        __pipeline_memcpy_async(&smh[(stage) * STAGEH + bOff],              \
                                bSrc + (size_t)(kt) * 16 * N, 16);          \
        __pipeline_commit();                                                \
    } while (0)

    wmma::fragment<wmma::accumulator, 16, 16, 16, float> acc[2][4];
#pragma unroll
    for (int mt = 0; mt < 2; mt++)
#pragma unroll
        for (int nt = 0; nt < 4; nt++)
            wmma::fill_fragment(acc[mt][nt], 0.0f);

    // prologue: tiles 0..2 -> stages 0..2
    GEMM_ISSUE(0, 0);
    GEMM_ISSUE(1, 1);
    GEMM_ISSUE(2, 2);

    const int NK = EMB / 16;   // 64
    for (int kt = 0; kt < NK; kt++) {
        const int rem = NK - kt;     // groups outstanding = min(3, rem)
        if (rem >= 3)      __pipeline_wait_prior(2);
        else if (rem == 2) __pipeline_wait_prior(1);
        else               __pipeline_wait_prior(0);
        __syncthreads();

        const __half* As = smh + (kt & 3) * STAGEH;
        const __half* Bs = As + ABUFH;
        {
            wmma::fragment<wmma::matrix_a, 16, 16, 16, __half,
                           wmma::row_major> af[2];
            wmma::fragment<wmma::matrix_b, 16, 16, 16, __half,
                           wmma::row_major> bf[4];
            wmma::load_matrix_sync(af[0], &As[wm * ALDH], ALDH);
            wmma::load_matrix_sync(af[1], &As[(wm + 16) * ALDH], ALDH);
#pragma unroll
            for (int nt = 0; nt < 4; nt++)
                wmma::load_matrix_sync(bf[nt], &Bs[wn + nt * 16], BLDH);
#pragma unroll
            for (int mt = 0; mt < 2; mt++)
#pragma unroll
                for (int nt = 0; nt < 4; nt++)
                    wmma::mma_sync(acc[mt][nt], af[mt], bf[nt], acc[mt][nt]);
        }

        if (kt + 3 < NK)
            GEMM_ISSUE((kt + 3) & 3, kt + 3);
    }
#undef GEMM_ISSUE

    // ---- epilogue: stage via smem, fuse bias (+q-scale), write ----
    __syncthreads();           // all warps done reading pipeline buffers
    float* stg = (float*)smraw + warp * (16 * 68);
    const int r  = lane >> 1;
    const int c0 = (lane & 1) * 32;
#pragma unroll
    for (int mt = 0; mt < 2; mt++) {
#pragma unroll
        for (int nt = 0; nt < 4; nt++)
            wmma::store_matrix_sync(&stg[nt * 16], acc[mt][nt], 68,
                                    wmma::mem_row_major);
        __syncwarp();
        const int grow = bm * 128 + wm + mt * 16 + r;
        const int gcol = bn * 128 + wn + c0;   // multiple of 32
        const float qs = (qscale_flag && gcol < EMB) ? 0.125f : 1.0f;
#pragma unroll
        for (int j = 0; j < 32; j += 4) {
            float4 v = *(const float4*)&stg[r * 68 + c0 + j];
            const float4 b = *(const float4*)&bias[gcol + j];
            v.x = (v.x + b.x) * qs;
            v.y = (v.y + b.y) * qs;
            v.z = (v.z + b.z) * qs;
            v.w = (v.w + b.w) * qs;
            if (Ch) st_half4(&Ch[(size_t)grow * N + gcol + j], v);
            else    *(float4*)&Cf[(size_t)grow * N + gcol + j] = v;
        }
        __syncwarp();
    }
}

// ---------------------------------------------------------------------------
// Flash attention (fp16 S and PV), cp.async double-buffered K/V.
// Block = 128 queries of one (b,h), 128 threads = 4 warps, warp owns 32 rows.
// Per tile: wait -> ONE syncthreads -> issue next fill -> compute (fill of
// kt+1 overlaps compute of kt). Warp-uniform max; ones-column row sums;
// fragment-resident O; half in / half out.
// ---------------------------------------------------------------------------
#define QLDH 72     // halfs (64 + 8)
#define KLDH 72
#define VLDH 88     // halfs (80 + 8); col 64 = ones
#define PLD  68     // floats (S / O staging)
#define PLDH 72     // halfs (P for mma)
#define KBUF_B (64 * KLDH * 2)     // 9216
#define VBUF_B (64 * VLDH * 2)     // 11264
#define AT_Q_B  0
#define AT_K0_B (AT_Q_B + 128 * QLDH * 2)          // 18432
#define AT_V0_B (AT_K0_B + 2 * KBUF_B)             // 36864
#define AT_P_B  (AT_V0_B + 2 * VBUF_B)             // 59392
#define AT_PH_B (AT_P_B + 128 * PLD * 4)           // 94208
#define ATTN_SMEM_BYTES (AT_PH_B + 128 * PLDH * 2) // 112640

__global__ __launch_bounds__(128) void attn_wmma_kernel()
{
    extern __shared__ char smraw[];
    __half* Qs = (__half*)(smraw + AT_Q_B);   // [128][QLDH]
    float*  Ps = (float*)(smraw + AT_P_B);    // [128][PLD] float S / O
    __half* Ph = (__half*)(smraw + AT_PH_B);  // [128][PLDH] half P

    const int tid  = threadIdx.x;
    const int lane = tid & 31, warp = tid >> 5;
    const int qb = warp * 32;
    const int rowIdx = lane >> 1, half = lane & 1;

    const int qt = blockIdx.x;           // 0..15
    const int bh = blockIdx.y;           // 0..63
    const int bb = bh >> 4, h = bh & (NH - 1);
    const size_t rowbase = (size_t)bb * SEQ;
    const int qcol = h * HS, kcol = EMB + h * HS, vcol = 2 * EMB + h * HS;

#define ATTN_ISSUE_KV(buf, kt)                                              \
    do {                                                                    \
        __half* Kd = (__half*)(smraw + AT_K0_B + (buf) * KBUF_B);           \
        __half* Vd = (__half*)(smraw + AT_V0_B + (buf) * VBUF_B);           \
        const __half* base = qkv_h + (rowbase + (kt) * 64) * N3;            \
        for (int i = tid; i < 512; i += 128) {                              \
            const int row = i >> 3, d = (i & 7) * 8;                        \
            __pipeline_memcpy_async(&Kd[row * KLDH + d],                    \
                                    base + (size_t)row * N3 + kcol + d, 16);\
            __pipeline_memcpy_async(&Vd[row * VLDH + d],                    \
                                    base + (size_t)row * N3 + vcol + d, 16);\
        }                                                                   \
        __pipeline_commit();                                                \
    } while (0)

    // Q tile: pure copy (pre-scaled, pre-biased)
    for (int i = tid * 8; i < 128 * HS; i += 128 * 8) {
        const int rr = i >> 6, d = i & 63;
        *(uint4*)&Qs[rr * QLDH + d] = *(const uint4*)(
            qkv_h + (rowbase + qt * 128 + rr) * N3 + qcol + d);
    }
    // ones-column region in BOTH V buffers (cols 64..79; only 64 = 1)
    for (int i = tid; i < 64 * 16; i += 128) {
        const int rr = i >> 4, c = 64 + (i & 15);
        const __half v = (c == 64) ? __float2half(1.0f) : __float2half(0.0f);
        ((__half*)(smraw + AT_V0_B))[rr * VLDH + c] = v;
        ((__half*)(smraw + AT_V0_B + VBUF_B))[rr * VLDH + c] = v;
    }
    // prologue: fill tile 0 into buf 0
    ATTN_ISSUE_KV(0, 0);

    wmma::fragment<wmma::accumulator, 16, 16, 16, float> pv[2][5];
#pragma unroll
    for (int mt = 0; mt < 2; mt++)
#pragma unroll
        for (int nt = 0; nt < 5; nt++)
            wmma::fill_fragment(pv[mt][nt], 0.0f);
    float mW = -1e30f;

    for (int kt = 0; kt < SEQ / 64; kt++) {
        __pipeline_wait_prior(0);
        __syncthreads();
        if (kt + 1 < SEQ / 64)
            ATTN_ISSUE_KV((kt + 1) & 1, kt + 1);

        const __half* Ks = (__half*)(smraw + AT_K0_B + (kt & 1) * KBUF_B);
        const __half* Vs = (__half*)(smraw + AT_V0_B + (kt & 1) * VBUF_B);

        // ---- S = Q @ K^T ----
        wmma::fragment<wmma::accumulator, 16, 16, 16, float> sacc[2][4];
#pragma unroll
        for (int mt = 0; mt < 2; mt++)
#pragma unroll
            for (int nt = 0; nt < 4; nt++)
                wmma::fill_fragment(sacc[mt][nt], 0.0f);
#pragma unroll
        for (int d0 = 0; d0 < HS; d0 += 16) {
            wmma::fragment<wmma::matrix_a, 16, 16, 16, __half,
                           wmma::row_major> af[2];
            wmma::load_matrix_sync(af[0], &Qs[qb * QLDH + d0], QLDH);
            wmma::load_matrix_sync(af[1], &Qs[(qb + 16) * QLDH + d0], QLDH);
#pragma unroll
            for (int nt = 0; nt < 4; nt++) {
                wmma::fragment<wmma::matrix_b, 16, 16, 16, __half,
                               wmma::col_major> bf;
                wmma::load_matrix_sync(bf, &Ks[(nt * 16) * KLDH + d0], KLDH);
#pragma unroll
                for (int mt = 0; mt < 2; mt++)
                    wmma::mma_sync(sacc[mt][nt], af[mt], bf, sacc[mt][nt]);
            }
        }

        // ---- warp-uniform online max ----
        float mx = -1e30f;
#pragma unroll
        for (int mt = 0; mt < 2; mt++)
#pragma unroll
            for (int nt = 0; nt < 4; nt++)
#pragma unroll
                for (int e = 0; e < sacc[mt][nt].num_elements; e++)
                    mx = fmaxf(mx, sacc[mt][nt].x[e]);
#pragma unroll
        for (int off = 16; off > 0; off >>= 1)
            mx = fmaxf(mx, __shfl_xor_sync(0xffffffff, mx, off));
        const float mn = fmaxf(mW, mx);
        const float corr = __expf(mW - mn);
        mW = mn;

        // ---- O *= corr ----
#pragma unroll
        for (int mt = 0; mt < 2; mt++)
#pragma unroll
            for (int nt = 0; nt < 5; nt++)
#pragma unroll
                for (int e = 0; e < pv[mt][nt].num_elements; e++)
                    pv[mt][nt].x[e] *= corr;

        // ---- P = exp(S - m) -> float tile -> half tile ----
#pragma unroll
        for (int mt = 0; mt < 2; mt++)
#pragma unroll
            for (int nt = 0; nt < 4; nt++) {
#pragma unroll
                for (int e = 0; e < sacc[mt][nt].num_elements; e++)
                    sacc[mt][nt].x[e] = __expf(sacc[mt][nt].x[e] - mn);
                wmma::store_matrix_sync(&Ps[(qb + mt * 16) * PLD + nt * 16],
                                        sacc[mt][nt], PLD,
                                        wmma::mem_row_major);
            }
        __syncwarp();
        for (int i = lane * 4; i < 32 * 64; i += 32 * 4) {
            const int rr = qb + (i >> 6), c = i & 63;
            st_half4(&Ph[rr * PLDH + c], *(const float4*)&Ps[rr * PLD + c]);
        }
        __syncwarp();

        // ---- O += P @ V' (ones col -> pv[mt][4] col0 = l) ----
#pragma unroll
        for (int kk = 0; kk < 64; kk += 16) {
            wmma::fragment<wmma::matrix_a, 16, 16, 16, __half,
                           wmma::row_major> af[2];
            wmma::load_matrix_sync(af[0], &Ph[qb * PLDH + kk], PLDH);
            wmma::load_matrix_sync(af[1], &Ph[(qb + 16) * PLDH + kk], PLDH);
#pragma unroll
            for (int nt = 0; nt < 5; nt++) {
                wmma::fragment<wmma::matrix_b, 16, 16, 16, __half,
                               wmma::row_major> bf;
                wmma::load_matrix_sync(bf, &Vs[kk * VLDH + nt * 16], VLDH);
#pragma unroll
                for (int mt = 0; mt < 2; mt++)
                    wmma::mma_sync(pv[mt][nt], af[mt], bf, pv[mt][nt]);
            }
        }
    }
#undef ATTN_ISSUE_KV

    // ---- epilogue: extract l, normalize, write half ----
    wmma::store_matrix_sync(&Ps[qb * PLD], pv[0][4], PLD,
                            wmma::mem_row_major);
    wmma::store_matrix_sync(&Ps[(qb + 16) * PLD], pv[1][4], PLD,
                            wmma::mem_row_major);
    __syncwarp();
    const float l0 = Ps[(qb + rowIdx) * PLD + 0];
    const float l1 = Ps[(qb + 16 + rowIdx) * PLD + 0];
    __syncwarp();
#pragma unroll
    for (int mt = 0; mt < 2; mt++)
#pragma unroll
        for (int nt = 0; nt < 4; nt++)
            wmma::store_matrix_sync(&Ps[(qb + mt * 16) * PLD + nt * 16],
                                    pv[mt][nt], PLD, wmma::mem_row_major);
    __syncwarp();

#pragma unroll
    for (int mt = 0; mt < 2; mt++) {
        const float inv = 1.0f / (mt ? l1 : l0);
        const int r = qb + mt * 16 + rowIdx;
        __half* orow = g_att_h + (size_t)(rowbase + qt * 128 + r) * EMB
                       + h * HS + half * 32;
        const float* prow = &Ps[r * PLD + half * 32];
#pragma unroll
        for (int j = 0; j < 32; j += 4) {
            const float4 o4 = *(const float4*)&prow[j];
            st_half4(&orow[j], make_float4(o4.x * inv, o4.y * inv,
                                           o4.z * inv, o4.w * inv));
        }
    }
}

// ---------------------------------------------------------------------------
extern "C" void kernel_launch(void* const* d_in, const int* in_sizes, int n_in,
                              void* d_out, int out_size)
{
    const float* x     = (const float*)d_in[0];
    const float* w_qkv = (const float*)d_in[1];
    const float* b_qkv = (const float*)d_in[2];
    const float* w_out = (const float*)d_in[3];
    const float* b_out = (const float*)d_in[4];
    float* out = (float*)d_out;

    __half *xh_p, *wq_p, *wo_p, *qkv_p, *att_p;
    cudaGetSymbolAddress((void**)&xh_p,  x_h);
    cudaGetSymbolAddress((void**)&wq_p,  wqkv_h);
    cudaGetSymbolAddress((void**)&wo_p,  wout_h);
    cudaGetSymbolAddress((void**)&qkv_p, qkv_h);
    cudaGetSymbolAddress((void**)&att_p, g_att_h);

    // convert inputs to half
    f2h_kernel<<<(MROWS * EMB) / 2048, 256>>>(x, xh_p);
    f2h_kernel<<<(EMB * N3) / 2048, 256>>>(w_qkv, wq_p);
    f2h_kernel<<<(EMB * EMB) / 2048, 256>>>(w_out, wo_p);

    // QKV projection: bias fused, q-cols pre-scaled by 1/8, half out
    gemm_h_kernel<<<dim3(N3 / 128, MROWS / 128), 256, GEMM_SMEM_BYTES>>>(
        xh_p, wq_p, b_qkv, qkv_p, nullptr, N3, 1);

    cudaFuncSetAttribute(attn_wmma_kernel,
                         cudaFuncAttributeMaxDynamicSharedMemorySize,
                         ATTN_SMEM_BYTES);
    attn_wmma_kernel<<<dim3(SEQ / 128, BATCH * NH), 128, ATTN_SMEM_BYTES>>>();

    // Output projection: bias fused, float out
    gemm_h_kernel<<<dim3(EMB / 128, MROWS / 128), 256, GEMM_SMEM_BYTES>>>(
        att_p, wo_p, b_out, nullptr, out, EMB, 0);
}